// round 5
// baseline (speedup 1.0000x reference)
#include <cuda_runtime.h>
#include <cuda_bf16.h>
#include <cstdint>

#define SEQ 2048
#define HD  64
#define NBH 32

__device__ float g_l[NBH * SEQ];

#define SWZ(x) ((x) ^ (((x) >> 3) & 0x70))

__device__ __forceinline__ uint32_t smem_u32(const void* p) {
    uint32_t a;
    asm("{ .reg .u64 t; cvta.to.shared.u64 t, %1; cvt.u32.u64 %0, t; }"
        : "=r"(a) : "l"(p));
    return a;
}
__device__ __forceinline__ void ldsm4(uint32_t* d, uint32_t a) {
    asm volatile("ldmatrix.sync.aligned.m8n8.x4.shared.b16 {%0,%1,%2,%3}, [%4];"
        : "=r"(d[0]), "=r"(d[1]), "=r"(d[2]), "=r"(d[3]) : "r"(a));
}
__device__ __forceinline__ void ldsm4t(uint32_t* d, uint32_t a) {
    asm volatile("ldmatrix.sync.aligned.m8n8.x4.trans.shared.b16 {%0,%1,%2,%3}, [%4];"
        : "=r"(d[0]), "=r"(d[1]), "=r"(d[2]), "=r"(d[3]) : "r"(a));
}
__device__ __forceinline__ void mma_bf16(float* c, const uint32_t* a,
                                         uint32_t b0, uint32_t b1) {
    asm volatile(
        "mma.sync.aligned.m16n8k16.row.col.f32.bf16.bf16.f32 "
        "{%0,%1,%2,%3}, {%4,%5,%6,%7}, {%8,%9}, {%0,%1,%2,%3};"
        : "+f"(c[0]), "+f"(c[1]), "+f"(c[2]), "+f"(c[3])
        : "r"(a[0]), "r"(a[1]), "r"(a[2]), "r"(a[3]), "r"(b0), "r"(b1));
}
__device__ __forceinline__ void split2(float x0, float x1, uint32_t& hi, uint32_t& lo) {
    __nv_bfloat162 h = __floats2bfloat162_rn(x0, x1);
    float r0 = x0 - __bfloat162float(h.x);
    float r1 = x1 - __bfloat162float(h.y);
    __nv_bfloat162 l = __floats2bfloat162_rn(r0, r1);
    hi = *reinterpret_cast<uint32_t*>(&h);
    lo = *reinterpret_cast<uint32_t*>(&l);
}
__device__ __forceinline__ uint32_t pack2(float x0, float x1) {
    __nv_bfloat162 h = __floats2bfloat162_rn(x0, x1);
    return *reinterpret_cast<uint32_t*>(&h);
}

// ---------------------------------------------------------------------------
// Single fused kernel: E=exp(mask(QK^T/8)) (+ zero-fill), rowsums, O=(E@V)/l,
// then in-place normalization of this block's causal rows: P = E/l.
// Block = 512 thr (16 warps: 8 Mrows x 2 Nhalves), tile M=128, N=128, d=64.
// ---------------------------------------------------------------------------
__global__ __launch_bounds__(512, 1) void k_attn(
    const float* __restrict__ Q, const float* __restrict__ K,
    const float* __restrict__ V, const float* __restrict__ mask,
    const int* __restrict__ mask_now,
    float* __restrict__ E, float* __restrict__ O)
{
    extern __shared__ char sm[];
    const uint32_t smb = smem_u32(sm);
    const int tid = threadIdx.x, lane = tid & 31, warp = tid >> 5;
    const int mrow = warp >> 1, nhalf = warp & 1;
    const int g = lane >> 3, r8 = lane & 7;
    const int qt = 15 - blockIdx.x, bh = blockIdx.y, b = bh >> 4;
    const int q0 = qt * 128;
    const int mn = mask_now[0];

    const uint32_t QHI = 0, QLO = 16384, KHI = 32768, KLO = 49152,
                   VHI = 65536, VLO = 81920;
    float* RS  = (float*)(sm + 98304);
    float* INV = (float*)(sm + 99328);
    float* Ob  = (float*)(sm + 32768);   // reuses KHI after mainloop

    // stage Q (pre-scaled by 1/8) into bf16 hi/lo planes
    {
        const float* Qg = Q + ((size_t)bh * SEQ + q0) * HD;
        for (int i = tid; i < 2048; i += 512) {
            int row = i >> 4, c4 = i & 15;
            float4 v = *(const float4*)(Qg + row * HD + c4 * 4);
            uint32_t h0, l0, h1, l1;
            split2(v.x * 0.125f, v.y * 0.125f, h0, l0);
            split2(v.z * 0.125f, v.w * 0.125f, h1, l1);
            uint32_t off = SWZ(row * 128 + c4 * 8);
            *(uint2*)(sm + QHI + off) = make_uint2(h0, h1);
            *(uint2*)(sm + QLO + off) = make_uint2(l0, l1);
        }
    }

    // zero-fill E cols [q0+128, SEQ) for this block's rows (coalesced)
    {
        const int c0 = q0 + 128;
        const int w = (SEQ - c0) >> 2;
        for (int r = warp; r < 128; r += 16) {
            float4* rowp = (float4*)(E + ((size_t)bh * SEQ + q0 + r) * SEQ + c0);
            for (int cc = lane; cc < w; cc += 32)
                rowp[cc] = make_float4(0.f, 0.f, 0.f, 0.f);
        }
    }

    const int rl = mrow * 16 + (lane >> 2), rh = rl + 8;
    const int qrl = q0 + rl, qrh = q0 + rh;
    const bool mql = mask[(size_t)b * SEQ + qrl] != 0.f;
    const bool mqh = mask[(size_t)b * SEQ + qrh] != 0.f;

    __syncthreads();   // Q planes ready

    // hoist Q fragments (planes persist across all tiles)
    uint32_t qfh[4][4], qfl[4][4];
    {
        int row = mrow * 16 + ((g & 1) << 3) + r8;
        #pragma unroll
        for (int s = 0; s < 4; s++) {
            int ch = 2 * s + (g >> 1);
            uint32_t off = SWZ(row * 128 + ch * 16);
            ldsm4(qfh[s], smb + QHI + off);
            ldsm4(qfl[s], smb + QLO + off);
        }
    }

    float o[8][4];
    #pragma unroll
    for (int j = 0; j < 8; j++)
        o[j][0] = o[j][1] = o[j][2] = o[j][3] = 0.f;
    float rsl = 0.f, rsh = 0.f;

    for (int t = 0; t <= qt; t++) {
        const int k0 = t * 128;
        __syncthreads();
        {
            const float* Kg = K + ((size_t)bh * SEQ + k0) * HD;
            const float* Vg = V + ((size_t)bh * SEQ + k0) * HD;
            for (int i = tid; i < 2048; i += 512) {
                int row = i >> 4, c4 = i & 15;
                uint32_t off = SWZ(row * 128 + c4 * 8);
                float4 v = *(const float4*)(Kg + row * HD + c4 * 4);
                uint32_t h0, l0, h1, l1;
                split2(v.x, v.y, h0, l0); split2(v.z, v.w, h1, l1);
                *(uint2*)(sm + KHI + off) = make_uint2(h0, h1);
                *(uint2*)(sm + KLO + off) = make_uint2(l0, l1);
                v = *(const float4*)(Vg + row * HD + c4 * 4);
                split2(v.x, v.y, h0, l0); split2(v.z, v.w, h1, l1);
                *(uint2*)(sm + VHI + off) = make_uint2(h0, h1);
                *(uint2*)(sm + VLO + off) = make_uint2(l0, l1);
            }
        }
        __syncthreads();

        const bool diag = (t == qt);
        const int kb = k0 + nhalf * 64 + 2 * (lane & 3);

        // warps entirely above the diagonal: write zeros, skip compute
        if (diag && nhalf == 1 && mrow < 4) {
            #pragma unroll
            for (int jl2 = 0; jl2 < 8; jl2++) {
                int kc = kb + jl2 * 8;
                *(float2*)(E + ((size_t)bh * SEQ + qrl) * SEQ + kc) = make_float2(0.f, 0.f);
                *(float2*)(E + ((size_t)bh * SEQ + qrh) * SEQ + kc) = make_float2(0.f, 0.f);
            }
            continue;
        }

        #pragma unroll
        for (int h = 0; h < 2; h++) {
            float c[4][4];
            #pragma unroll
            for (int j = 0; j < 4; j++)
                c[j][0] = c[j][1] = c[j][2] = c[j][3] = 0.f;

            // ---- QK^T (bf16 x3) ----
            #pragma unroll
            for (int s = 0; s < 4; s++) {
                #pragma unroll
                for (int pp = 0; pp < 2; pp++) {
                    int p = 2 * h + pp;
                    uint32_t kh[4], kl[4];
                    int row = nhalf * 64 + p * 16 + ((g >> 1) << 3) + r8;
                    int ch  = 2 * s + (g & 1);
                    uint32_t off = SWZ(row * 128 + ch * 16);
                    ldsm4(kh, smb + KHI + off);
                    ldsm4(kl, smb + KLO + off);
                    mma_bf16(c[2 * pp],     qfl[s], kh[0], kh[1]);
                    mma_bf16(c[2 * pp],     qfh[s], kl[0], kl[1]);
                    mma_bf16(c[2 * pp],     qfh[s], kh[0], kh[1]);
                    mma_bf16(c[2 * pp + 1], qfl[s], kh[2], kh[3]);
                    mma_bf16(c[2 * pp + 1], qfh[s], kl[2], kl[3]);
                    mma_bf16(c[2 * pp + 1], qfh[s], kh[2], kh[3]);
                }
            }

            // ---- mask + exp + rowsum + store E ----
            #pragma unroll
            for (int jl = 0; jl < 4; jl++) {
                int kc = kb + (4 * h + jl) * 8;
                c[jl][0] = (mql && (!diag || kc     + mn <= qrl)) ? __expf(c[jl][0]) : 0.f;
                c[jl][1] = (mql && (!diag || kc + 1 + mn <= qrl)) ? __expf(c[jl][1]) : 0.f;
                c[jl][2] = (mqh && (!diag || kc     + mn <= qrh)) ? __expf(c[jl][2]) : 0.f;
                c[jl][3] = (mqh && (!diag || kc + 1 + mn <= qrh)) ? __expf(c[jl][3]) : 0.f;
                rsl += c[jl][0] + c[jl][1];
                rsh += c[jl][2] + c[jl][3];
                *(float2*)(E + ((size_t)bh * SEQ + qrl) * SEQ + kc) =
                    make_float2(c[jl][0], c[jl][1]);
                *(float2*)(E + ((size_t)bh * SEQ + qrh) * SEQ + kc) =
                    make_float2(c[jl][2], c[jl][3]);
            }

            // ---- PV (bf16 x3): A = E hi+lo (regs), B = V hi+lo (ldsm.trans) ----
            #pragma unroll
            for (int sl = 0; sl < 2; sl++) {
                int s = 2 * h + sl;
                uint32_t ahi[4], alo[4];
                split2(c[2 * sl][0],     c[2 * sl][1],     ahi[0], alo[0]);
                split2(c[2 * sl][2],     c[2 * sl][3],     ahi[1], alo[1]);
                split2(c[2 * sl + 1][0], c[2 * sl + 1][1], ahi[2], alo[2]);
                split2(c[2 * sl + 1][2], c[2 * sl + 1][3], ahi[3], alo[3]);
                int krow = nhalf * 64 + s * 16 + ((g & 1) << 3) + r8;
                #pragma unroll
                for (int p = 0; p < 4; p++) {
                    uint32_t bhr[4], blr[4];
                    int ch = 2 * p + (g >> 1);
                    uint32_t off = SWZ(krow * 128 + ch * 16);
                    ldsm4t(bhr, smb + VHI + off);
                    ldsm4t(blr, smb + VLO + off);
                    mma_bf16(o[2 * p],     alo, bhr[0], bhr[1]);
                    mma_bf16(o[2 * p],     ahi, blr[0], blr[1]);
                    mma_bf16(o[2 * p],     ahi, bhr[0], bhr[1]);
                    mma_bf16(o[2 * p + 1], alo, bhr[2], bhr[3]);
                    mma_bf16(o[2 * p + 1], ahi, blr[2], blr[3]);
                    mma_bf16(o[2 * p + 1], ahi, bhr[2], bhr[3]);
                }
            }
        }
    }

    // ---- rowsums -> l, inv ----
    rsl += __shfl_xor_sync(0xffffffffu, rsl, 1);
    rsl += __shfl_xor_sync(0xffffffffu, rsl, 2);
    rsh += __shfl_xor_sync(0xffffffffu, rsh, 1);
    rsh += __shfl_xor_sync(0xffffffffu, rsh, 2);
    if ((lane & 3) == 0) {
        RS[nhalf * 128 + rl] = rsl;
        RS[nhalf * 128 + rh] = rsh;
    }
    __syncthreads();
    if (tid < 128) {
        float l = RS[tid] + RS[128 + tid];
        g_l[bh * SEQ + q0 + tid] = l;
        INV[tid] = (l > 0.f) ? (1.f / l) : 0.f;
    }
    __syncthreads();

    // ---- cross-warp O reduce (+ scale) and store ----
    const int dcol = 2 * (lane & 3);
    if (nhalf == 1) {
        #pragma unroll
        for (int j = 0; j < 8; j++) {
            *(float2*)(Ob + rl * 68 + j * 8 + dcol) = make_float2(o[j][0], o[j][1]);
            *(float2*)(Ob + rh * 68 + j * 8 + dcol) = make_float2(o[j][2], o[j][3]);
        }
    }
    __syncthreads();
    if (nhalf == 0) {
        float il = INV[rl], ih = INV[rh];
        #pragma unroll
        for (int j = 0; j < 8; j++) {
            float2 p0 = *(float2*)(Ob + rl * 68 + j * 8 + dcol);
            float2 p1 = *(float2*)(Ob + rh * 68 + j * 8 + dcol);
            *(float2*)(O + ((size_t)bh * SEQ + qrl) * HD + j * 8 + dcol) =
                make_float2((o[j][0] + p0.x) * il, (o[j][1] + p0.y) * il);
            *(float2*)(O + ((size_t)bh * SEQ + qrh) * HD + j * 8 + dcol) =
                make_float2((o[j][2] + p1.x) * ih, (o[j][3] + p1.y) * ih);
        }
    }

    // ---- in-place normalization of this block's causal rows: P = E/l ----
    // (cols beyond kmax inside the last float4 are exact zeros; scaling is a no-op)
    for (int r = warp; r < 128; r += 16) {
        const int q = q0 + r;
        const float inv = INV[r];
        const int nf4 = (q - mn + 4) >> 2;   // float4s covering [0, q-mn]
        float4* rowp = (float4*)(E + ((size_t)bh * SEQ + q) * SEQ);
        for (int cc = lane; cc < nf4; cc += 32) {
            float4 v = rowp[cc];
            v.x *= inv; v.y *= inv; v.z *= inv; v.w *= inv;
            rowp[cc] = v;
        }
    }
}

// ---------------------------------------------------------------------------
extern "C" void kernel_launch(void* const* d_in, const int* in_sizes, int n_in,
                              void* d_out, int out_size)
{
    const float* Q        = (const float*)d_in[0];
    const float* K        = (const float*)d_in[1];
    const float* V        = (const float*)d_in[2];
    const float* mask     = (const float*)d_in[3];
    const int*   mask_now = (const int*)d_in[4];

    float* O = (float*)d_out;                      // [B,H,S,D]
    float* P = O + (size_t)NBH * SEQ * HD;         // [B,H,S,S]

    cudaFuncSetAttribute(k_attn, cudaFuncAttributeMaxDynamicSharedMemorySize, 99840);

    k_attn<<<dim3(16, NBH), 512, 99840>>>(Q, K, V, mask, mask_now, P, O);
}

// round 6
// speedup vs baseline: 1.3221x; 1.3221x over previous
#include <cuda_runtime.h>
#include <cuda_bf16.h>
#include <cuda_fp16.h>
#include <cstdint>

#define SEQ 2048
#define HD  64
#define NBH 32

__device__ float g_l[NBH * SEQ];

#define SWZ(x) ((x) ^ (((x) >> 3) & 0x70))

__device__ __forceinline__ uint32_t smem_u32(const void* p) {
    uint32_t a;
    asm("{ .reg .u64 t; cvta.to.shared.u64 t, %1; cvt.u32.u64 %0, t; }"
        : "=r"(a) : "l"(p));
    return a;
}
__device__ __forceinline__ void ldsm4(uint32_t* d, uint32_t a) {
    asm volatile("ldmatrix.sync.aligned.m8n8.x4.shared.b16 {%0,%1,%2,%3}, [%4];"
        : "=r"(d[0]), "=r"(d[1]), "=r"(d[2]), "=r"(d[3]) : "r"(a));
}
__device__ __forceinline__ void ldsm4t(uint32_t* d, uint32_t a) {
    asm volatile("ldmatrix.sync.aligned.m8n8.x4.trans.shared.b16 {%0,%1,%2,%3}, [%4];"
        : "=r"(d[0]), "=r"(d[1]), "=r"(d[2]), "=r"(d[3]) : "r"(a));
}
__device__ __forceinline__ void mma_bf16(float* c, const uint32_t* a,
                                         uint32_t b0, uint32_t b1) {
    asm volatile(
        "mma.sync.aligned.m16n8k16.row.col.f32.bf16.bf16.f32 "
        "{%0,%1,%2,%3}, {%4,%5,%6,%7}, {%8,%9}, {%0,%1,%2,%3};"
        : "+f"(c[0]), "+f"(c[1]), "+f"(c[2]), "+f"(c[3])
        : "r"(a[0]), "r"(a[1]), "r"(a[2]), "r"(a[3]), "r"(b0), "r"(b1));
}
__device__ __forceinline__ void mma_f16(float* c, const uint32_t* a,
                                        uint32_t b0, uint32_t b1) {
    asm volatile(
        "mma.sync.aligned.m16n8k16.row.col.f32.f16.f16.f32 "
        "{%0,%1,%2,%3}, {%4,%5,%6,%7}, {%8,%9}, {%0,%1,%2,%3};"
        : "+f"(c[0]), "+f"(c[1]), "+f"(c[2]), "+f"(c[3])
        : "r"(a[0]), "r"(a[1]), "r"(a[2]), "r"(a[3]), "r"(b0), "r"(b1));
}
// fp32 pair -> packed bf16 hi word + residual lo word
__device__ __forceinline__ void split2(float x0, float x1, uint32_t& hi, uint32_t& lo) {
    __nv_bfloat162 h = __floats2bfloat162_rn(x0, x1);
    __nv_bfloat162 l = __floats2bfloat162_rn(x0 - __bfloat162float(h.x),
                                             x1 - __bfloat162float(h.y));
    hi = *reinterpret_cast<uint32_t*>(&h);
    lo = *reinterpret_cast<uint32_t*>(&l);
}
// fp32 pair -> packed fp16 hi word + residual lo word
__device__ __forceinline__ void split2h(float x0, float x1, uint32_t& hi, uint32_t& lo) {
    __half2 h = __floats2half2_rn(x0, x1);
    float2 hf = __half22float2(h);
    __half2 l = __floats2half2_rn(x0 - hf.x, x1 - hf.y);
    hi = *reinterpret_cast<uint32_t*>(&h);
    lo = *reinterpret_cast<uint32_t*>(&l);
}
__device__ __forceinline__ uint32_t pack2h(float x0, float x1) {
    __half2 h = __floats2half2_rn(x0, x1);
    return *reinterpret_cast<uint32_t*>(&h);
}

// smem map (bytes):
//  QHI 0..16K, QLO 16K..32K                       (bf16 planes, persistent)
//  K buf b: 32768+b*32768 (HI) / +16384 (LO)      (bf16, double-buffered)
//  V buf b: 98304+b*32768 (HI) / +16384 (LO)      (fp16, double-buffered)
//  RS 163840 (1KB), INV 164864 (512B)             total 165376
//  Ob reuses 32768.. after mainloop
#define KB(b) (32768u + (b) * 32768u)
#define VB(b) (98304u + (b) * 32768u)

__global__ __launch_bounds__(512, 1) void k_attn(
    const float* __restrict__ Q, const float* __restrict__ K,
    const float* __restrict__ V, const float* __restrict__ mask,
    const int* __restrict__ mask_now,
    float* __restrict__ E, float* __restrict__ O)
{
    extern __shared__ char sm[];
    const uint32_t smb = smem_u32(sm);
    const int tid = threadIdx.x, lane = tid & 31, warp = tid >> 5;
    const int mrow = warp >> 1, nhalf = warp & 1;
    const int g = lane >> 3, r8 = lane & 7;
    const int qt = 15 - blockIdx.x, bh = blockIdx.y, b = bh >> 4;
    const int q0 = qt * 128;
    const int mn = mask_now[0];

    float* RS  = (float*)(sm + 163840);
    float* INV = (float*)(sm + 164864);
    float* Ob  = (float*)(sm + 32768);

    // ---- stage Q planes (pre-scaled by 1/8) + tile-0 K/V planes ----
    {
        const float* Qg = Q + ((size_t)bh * SEQ + q0) * HD;
        const float* Kg = K + (size_t)bh * SEQ * HD;
        const float* Vg = V + (size_t)bh * SEQ * HD;
        #pragma unroll
        for (int it = 0; it < 4; it++) {
            int i = tid + it * 512;
            int row = i >> 4, c4 = i & 15;
            uint32_t off = SWZ(row * 128 + c4 * 8);
            uint32_t h0, l0, h1, l1;
            float4 v = *(const float4*)(Qg + row * HD + c4 * 4);
            split2(v.x * 0.125f, v.y * 0.125f, h0, l0);
            split2(v.z * 0.125f, v.w * 0.125f, h1, l1);
            *(uint2*)(sm + 0     + off) = make_uint2(h0, h1);
            *(uint2*)(sm + 16384 + off) = make_uint2(l0, l1);
            v = *(const float4*)(Kg + row * HD + c4 * 4);
            split2(v.x, v.y, h0, l0); split2(v.z, v.w, h1, l1);
            *(uint2*)(sm + KB(0)         + off) = make_uint2(h0, h1);
            *(uint2*)(sm + KB(0) + 16384 + off) = make_uint2(l0, l1);
            v = *(const float4*)(Vg + row * HD + c4 * 4);
            split2h(v.x, v.y, h0, l0); split2h(v.z, v.w, h1, l1);
            *(uint2*)(sm + VB(0)         + off) = make_uint2(h0, h1);
            *(uint2*)(sm + VB(0) + 16384 + off) = make_uint2(l0, l1);
        }
    }

    // zero-fill E cols [q0+128, SEQ)
    {
        const int c0 = q0 + 128;
        const int w = (SEQ - c0) >> 2;
        for (int r = warp; r < 128; r += 16) {
            float4* rowp = (float4*)(E + ((size_t)bh * SEQ + q0 + r) * SEQ + c0);
            for (int cc = lane; cc < w; cc += 32)
                rowp[cc] = make_float4(0.f, 0.f, 0.f, 0.f);
        }
    }

    const int rl = mrow * 16 + (lane >> 2), rh = rl + 8;
    const int qrl = q0 + rl, qrh = q0 + rh;
    const bool mql = mask[(size_t)b * SEQ + qrl] != 0.f;
    const bool mqh = mask[(size_t)b * SEQ + qrh] != 0.f;
    const int qrow = mrow * 16 + ((g & 1) << 3) + r8;   // ldsm row for Q/A frags

    __syncthreads();

    // hoist Q-hi fragments only (QLO reloaded in-loop to save registers)
    uint32_t qfh[4][4];
    #pragma unroll
    for (int s = 0; s < 4; s++)
        ldsm4(qfh[s], smb + 0 + SWZ(qrow * 128 + (2 * s + (g >> 1)) * 16));

    float o[8][4];
    #pragma unroll
    for (int j = 0; j < 8; j++)
        o[j][0] = o[j][1] = o[j][2] = o[j][3] = 0.f;
    float rsl = 0.f, rsh = 0.f;

    for (int t = 0; t <= qt; t++) {
        const int cur = t & 1, nxt = cur ^ 1;
        const bool hasNext = (t < qt);
        const uint32_t KHIc = KB(cur), KLOc = KB(cur) + 16384;
        const uint32_t VHIc = VB(cur), VLOc = VB(cur) + 16384;
        const int k0 = t * 128;
        const bool diag = (t == qt);
        const int kb = k0 + nhalf * 64 + 2 * (lane & 3);
        const bool skipw = diag && nhalf == 1 && mrow < 4;

        // prefetch next K tile into registers (hidden by h=0 compute)
        float4 kreg[4];
        if (hasNext) {
            const float* Kg = K + ((size_t)bh * SEQ + k0 + 128) * HD;
            #pragma unroll
            for (int it = 0; it < 4; it++) {
                int i = tid + it * 512;
                kreg[it] = *(const float4*)(Kg + (i >> 4) * HD + (i & 15) * 4);
            }
        }

        if (skipw) {
            #pragma unroll
            for (int jl2 = 0; jl2 < 8; jl2++) {
                int kc = kb + jl2 * 8;
                *(float2*)(E + ((size_t)bh * SEQ + qrl) * SEQ + kc) = make_float2(0.f, 0.f);
                *(float2*)(E + ((size_t)bh * SEQ + qrh) * SEQ + kc) = make_float2(0.f, 0.f);
            }
        }

        #pragma unroll
        for (int h = 0; h < 2; h++) {
            if (h == 1) {
                // convert K(t+1) into alternate planes; prefetch next V tile
                if (hasNext) {
                    #pragma unroll
                    for (int it = 0; it < 4; it++) {
                        int i = tid + it * 512;
                        int row = i >> 4, c4 = i & 15;
                        uint32_t off = SWZ(row * 128 + c4 * 8);
                        uint32_t h0, l0, h1, l1;
                        split2(kreg[it].x, kreg[it].y, h0, l0);
                        split2(kreg[it].z, kreg[it].w, h1, l1);
                        *(uint2*)(sm + KB(nxt)         + off) = make_uint2(h0, h1);
                        *(uint2*)(sm + KB(nxt) + 16384 + off) = make_uint2(l0, l1);
                        const float* Vg = V + ((size_t)bh * SEQ + k0 + 128) * HD;
                        kreg[it] = *(const float4*)(Vg + row * HD + c4 * 4);
                    }
                }
            }
            if (skipw) continue;

            float c[4][4];
            #pragma unroll
            for (int j = 0; j < 4; j++)
                c[j][0] = c[j][1] = c[j][2] = c[j][3] = 0.f;

            // ---- QK^T (bf16 x3) ----
            #pragma unroll
            for (int s = 0; s < 4; s++) {
                uint32_t qfl[4];
                ldsm4(qfl, smb + 16384 + SWZ(qrow * 128 + (2 * s + (g >> 1)) * 16));
                #pragma unroll
                for (int pp = 0; pp < 2; pp++) {
                    int p = 2 * h + pp;
                    uint32_t kh[4], kl[4];
                    int row = nhalf * 64 + p * 16 + ((g >> 1) << 3) + r8;
                    uint32_t off = SWZ(row * 128 + (2 * s + (g & 1)) * 16);
                    ldsm4(kh, smb + KHIc + off);
                    ldsm4(kl, smb + KLOc + off);
                    mma_bf16(c[2 * pp],     qfl,    kh[0], kh[1]);
                    mma_bf16(c[2 * pp],     qfh[s], kl[0], kl[1]);
                    mma_bf16(c[2 * pp],     qfh[s], kh[0], kh[1]);
                    mma_bf16(c[2 * pp + 1], qfl,    kh[2], kh[3]);
                    mma_bf16(c[2 * pp + 1], qfh[s], kl[2], kl[3]);
                    mma_bf16(c[2 * pp + 1], qfh[s], kh[2], kh[3]);
                }
            }

            // ---- mask + exp + rowsum + store E ----
            #pragma unroll
            for (int jl = 0; jl < 4; jl++) {
                int kc = kb + (4 * h + jl) * 8;
                c[jl][0] = (mql && (!diag || kc     + mn <= qrl)) ? __expf(c[jl][0]) : 0.f;
                c[jl][1] = (mql && (!diag || kc + 1 + mn <= qrl)) ? __expf(c[jl][1]) : 0.f;
                c[jl][2] = (mqh && (!diag || kc     + mn <= qrh)) ? __expf(c[jl][2]) : 0.f;
                c[jl][3] = (mqh && (!diag || kc + 1 + mn <= qrh)) ? __expf(c[jl][3]) : 0.f;
                rsl += c[jl][0] + c[jl][1];
                rsh += c[jl][2] + c[jl][3];
                *(float2*)(E + ((size_t)bh * SEQ + qrl) * SEQ + kc) =
                    make_float2(c[jl][0], c[jl][1]);
                *(float2*)(E + ((size_t)bh * SEQ + qrh) * SEQ + kc) =
                    make_float2(c[jl][2], c[jl][3]);
            }

            // ---- PV (fp16 x2): A = E fp16, B = V fp16 hi+lo ----
            #pragma unroll
            for (int sl = 0; sl < 2; sl++) {
                int s = 2 * h + sl;
                uint32_t af[4];
                af[0] = pack2h(c[2 * sl][0],     c[2 * sl][1]);
                af[1] = pack2h(c[2 * sl][2],     c[2 * sl][3]);
                af[2] = pack2h(c[2 * sl + 1][0], c[2 * sl + 1][1]);
                af[3] = pack2h(c[2 * sl + 1][2], c[2 * sl + 1][3]);
                int krow = nhalf * 64 + s * 16 + ((g & 1) << 3) + r8;
                #pragma unroll
                for (int p = 0; p < 4; p++) {
                    uint32_t bhr[4], blr[4];
                    uint32_t off = SWZ(krow * 128 + (2 * p + (g >> 1)) * 16);
                    ldsm4t(bhr, smb + VHIc + off);
                    ldsm4t(blr, smb + VLOc + off);
                    mma_f16(o[2 * p],     af, blr[0], blr[1]);
                    mma_f16(o[2 * p],     af, bhr[0], bhr[1]);
                    mma_f16(o[2 * p + 1], af, blr[2], blr[3]);
                    mma_f16(o[2 * p + 1], af, bhr[2], bhr[3]);
                }
            }
        }

        // convert V(t+1) (staged in kreg) into alternate fp16 planes
        if (hasNext) {
            #pragma unroll
            for (int it = 0; it < 4; it++) {
                int i = tid + it * 512;
                int row = i >> 4, c4 = i & 15;
                uint32_t off = SWZ(row * 128 + c4 * 8);
                uint32_t h0, l0, h1, l1;
                split2h(kreg[it].x, kreg[it].y, h0, l0);
                split2h(kreg[it].z, kreg[it].w, h1, l1);
                *(uint2*)(sm + VB(nxt)         + off) = make_uint2(h0, h1);
                *(uint2*)(sm + VB(nxt) + 16384 + off) = make_uint2(l0, l1);
            }
        }
        __syncthreads();
    }

    // ---- rowsums -> l, inv ----
    rsl += __shfl_xor_sync(0xffffffffu, rsl, 1);
    rsl += __shfl_xor_sync(0xffffffffu, rsl, 2);
    rsh += __shfl_xor_sync(0xffffffffu, rsh, 1);
    rsh += __shfl_xor_sync(0xffffffffu, rsh, 2);
    if ((lane & 3) == 0) {
        RS[nhalf * 128 + rl] = rsl;
        RS[nhalf * 128 + rh] = rsh;
    }
    __syncthreads();
    if (tid < 128) {
        float l = RS[tid] + RS[128 + tid];
        g_l[bh * SEQ + q0 + tid] = l;
        INV[tid] = (l > 0.f) ? (1.f / l) : 0.f;
    }
    __syncthreads();

    // ---- cross-warp O reduce (+ scale) and store ----
    const int dcol = 2 * (lane & 3);
    if (nhalf == 1) {
        #pragma unroll
        for (int j = 0; j < 8; j++) {
            *(float2*)(Ob + rl * 68 + j * 8 + dcol) = make_float2(o[j][0], o[j][1]);
            *(float2*)(Ob + rh * 68 + j * 8 + dcol) = make_float2(o[j][2], o[j][3]);
        }
    }
    __syncthreads();
    if (nhalf == 0) {
        float il = INV[rl], ih = INV[rh];
        #pragma unroll
        for (int j = 0; j < 8; j++) {
            float2 p0 = *(float2*)(Ob + rl * 68 + j * 8 + dcol);
            float2 p1 = *(float2*)(Ob + rh * 68 + j * 8 + dcol);
            *(float2*)(O + ((size_t)bh * SEQ + qrl) * HD + j * 8 + dcol) =
                make_float2((o[j][0] + p0.x) * il, (o[j][1] + p0.y) * il);
            *(float2*)(O + ((size_t)bh * SEQ + qrh) * HD + j * 8 + dcol) =
                make_float2((o[j][2] + p1.x) * ih, (o[j][3] + p1.y) * ih);
        }
    }

    // ---- in-place normalization of this block's causal rows: P = E/l ----
    for (int r = warp; r < 128; r += 16) {
        const int q = q0 + r;
        const float inv = INV[r];
        const int nf4 = (q - mn + 4) >> 2;
        float4* rowp = (float4*)(E + ((size_t)bh * SEQ + q) * SEQ);
        for (int cc = lane; cc < nf4; cc += 32) {
            float4 v = rowp[cc];
            v.x *= inv; v.y *= inv; v.z *= inv; v.w *= inv;
            rowp[cc] = v;
        }
    }
}

// ---------------------------------------------------------------------------
extern "C" void kernel_launch(void* const* d_in, const int* in_sizes, int n_in,
                              void* d_out, int out_size)
{
    const float* Q        = (const float*)d_in[0];
    const float* K        = (const float*)d_in[1];
    const float* V        = (const float*)d_in[2];
    const float* mask     = (const float*)d_in[3];
    const int*   mask_now = (const int*)d_in[4];

    float* O = (float*)d_out;                      // [B,H,S,D]
    float* P = O + (size_t)NBH * SEQ * HD;         // [B,H,S,S]

    cudaFuncSetAttribute(k_attn, cudaFuncAttributeMaxDynamicSharedMemorySize, 165376);

    k_attn<<<dim3(16, NBH), 512, 165376>>>(Q, K, V, mask, mask_now, P, O);
}

// round 7
// speedup vs baseline: 1.4344x; 1.0849x over previous
#include <cuda_runtime.h>
#include <cuda_bf16.h>
#include <cuda_fp16.h>
#include <cstdint>

#define SEQ 2048
#define HD  64
#define NBH 32

__device__ float g_l[NBH * SEQ];

#define SWZ(x) ((x) ^ (((x) >> 3) & 0x70))

__device__ __forceinline__ uint32_t smem_u32(const void* p) {
    uint32_t a;
    asm("{ .reg .u64 t; cvta.to.shared.u64 t, %1; cvt.u32.u64 %0, t; }"
        : "=r"(a) : "l"(p));
    return a;
}
__device__ __forceinline__ void ldsm4(uint32_t* d, uint32_t a) {
    asm volatile("ldmatrix.sync.aligned.m8n8.x4.shared.b16 {%0,%1,%2,%3}, [%4];"
        : "=r"(d[0]), "=r"(d[1]), "=r"(d[2]), "=r"(d[3]) : "r"(a));
}
__device__ __forceinline__ void ldsm4t(uint32_t* d, uint32_t a) {
    asm volatile("ldmatrix.sync.aligned.m8n8.x4.trans.shared.b16 {%0,%1,%2,%3}, [%4];"
        : "=r"(d[0]), "=r"(d[1]), "=r"(d[2]), "=r"(d[3]) : "r"(a));
}
__device__ __forceinline__ void mma_f16(float* c, const uint32_t* a,
                                        uint32_t b0, uint32_t b1) {
    asm volatile(
        "mma.sync.aligned.m16n8k16.row.col.f32.f16.f16.f32 "
        "{%0,%1,%2,%3}, {%4,%5,%6,%7}, {%8,%9}, {%0,%1,%2,%3};"
        : "+f"(c[0]), "+f"(c[1]), "+f"(c[2]), "+f"(c[3])
        : "r"(a[0]), "r"(a[1]), "r"(a[2]), "r"(a[3]), "r"(b0), "r"(b1));
}
// fp32 pair -> packed fp16 hi word + residual lo word
__device__ __forceinline__ void split2h(float x0, float x1, uint32_t& hi, uint32_t& lo) {
    __half2 h = __floats2half2_rn(x0, x1);
    float2 hf = __half22float2(h);
    __half2 l = __floats2half2_rn(x0 - hf.x, x1 - hf.y);
    hi = *reinterpret_cast<uint32_t*>(&h);
    lo = *reinterpret_cast<uint32_t*>(&l);
}
__device__ __forceinline__ uint32_t pack2h(float x0, float x1) {
    __half2 h = __floats2half2_rn(x0, x1);
    return *reinterpret_cast<uint32_t*>(&h);
}
// swizzled base for row r (128B rows): SWZ(lin) == swzrow(r) ^ (ch*16)
__device__ __forceinline__ uint32_t swzrow(int r) {
    uint32_t x = (uint32_t)r << 7;
    return x ^ ((x >> 3) & 0x70);
}

// smem map (bytes):
//  QF  0..16K                      (fp16 plane, persistent)
//  K buf b: 16384+b*32768 hi, +16384 lo   (fp16, double-buffered)  16K..80K
//  V buf b: 81920+b*32768 hi, +16384 lo   (fp16, double-buffered)  80K..144K
//  RS 147456 (1KB), INV 148480 (512B); total 148992
//  Ob reuses 16384.. after mainloop
#define KBUF(b) (16384u + (b) * 32768u)
#define VBUF(b) (81920u + (b) * 32768u)

__global__ __launch_bounds__(512, 1) void k_attn(
    const float* __restrict__ Q, const float* __restrict__ K,
    const float* __restrict__ V, const float* __restrict__ mask,
    const int* __restrict__ mask_now,
    float* __restrict__ E, float* __restrict__ O)
{
    extern __shared__ char sm[];
    const uint32_t smb = smem_u32(sm);
    const int tid = threadIdx.x, lane = tid & 31, warp = tid >> 5;
    const int mrow = warp >> 1, nhalf = warp & 1;
    const int g = lane >> 3, r8 = lane & 7;
    const int qt = 15 - blockIdx.x, bh = blockIdx.y, b = bh >> 4;
    const int q0 = qt * 128;
    const int mn = mask_now[0];

    float* RS  = (float*)(sm + 147456);
    float* INV = (float*)(sm + 148480);
    float* Ob  = (float*)(sm + 16384);

    // ---- stage Q plane (pre-scaled by 1/8) + tile-0 K/V planes ----
    {
        const float* Qg = Q + ((size_t)bh * SEQ + q0) * HD;
        const float* Kg = K + (size_t)bh * SEQ * HD;
        const float* Vg = V + (size_t)bh * SEQ * HD;
        #pragma unroll
        for (int it = 0; it < 4; it++) {
            int i = tid + it * 512;
            int row = i >> 4, c4 = i & 15;
            uint32_t off = SWZ(row * 128 + c4 * 8);
            uint32_t h0, l0, h1, l1;
            float4 v = *(const float4*)(Qg + row * HD + c4 * 4);
            *(uint2*)(sm + 0 + off) = make_uint2(
                pack2h(v.x * 0.125f, v.y * 0.125f),
                pack2h(v.z * 0.125f, v.w * 0.125f));
            v = *(const float4*)(Kg + row * HD + c4 * 4);
            split2h(v.x, v.y, h0, l0); split2h(v.z, v.w, h1, l1);
            *(uint2*)(sm + KBUF(0)         + off) = make_uint2(h0, h1);
            *(uint2*)(sm + KBUF(0) + 16384 + off) = make_uint2(l0, l1);
            v = *(const float4*)(Vg + row * HD + c4 * 4);
            split2h(v.x, v.y, h0, l0); split2h(v.z, v.w, h1, l1);
            *(uint2*)(sm + VBUF(0)         + off) = make_uint2(h0, h1);
            *(uint2*)(sm + VBUF(0) + 16384 + off) = make_uint2(l0, l1);
        }
    }

    // zero-fill E cols [q0+128, SEQ)
    {
        const int c0 = q0 + 128;
        const int w = (SEQ - c0) >> 2;
        for (int r = warp; r < 128; r += 16) {
            float4* rowp = (float4*)(E + ((size_t)bh * SEQ + q0 + r) * SEQ + c0);
            for (int cc = lane; cc < w; cc += 32)
                rowp[cc] = make_float4(0.f, 0.f, 0.f, 0.f);
        }
    }

    const int rl = mrow * 16 + (lane >> 2), rh = rl + 8;
    const int qrl = q0 + rl, qrh = q0 + rh;
    const bool mql = mask[(size_t)b * SEQ + qrl] != 0.f;
    const bool mqh = mask[(size_t)b * SEQ + qrh] != 0.f;

    // precomputed swizzled ldsm row-bases
    const uint32_t cbq = (uint32_t)(lane & 8) << 1;         // (g&1)*16
    const uint32_t cbv = (uint32_t)(g >> 1) << 4;           // (g>>1)*16
    uint32_t ka[4], va[4];
    #pragma unroll
    for (int p = 0; p < 4; p++)
        ka[p] = swzrow(nhalf * 64 + p * 16 + ((g >> 1) << 3) + r8);
    #pragma unroll
    for (int s = 0; s < 4; s++)
        va[s] = swzrow(nhalf * 64 + s * 16 + ((g & 1) << 3) + r8);
    const uint32_t qrowswz = swzrow(mrow * 16 + ((g & 1) << 3) + r8);

    __syncthreads();

    // hoist Q fragments (fp16, persistent plane)
    uint32_t qf[4][4];
    #pragma unroll
    for (int s = 0; s < 4; s++)
        ldsm4(qf[s], smb + (qrowswz ^ (cbv + (s << 5))));

    float o[8][4];
    #pragma unroll
    for (int j = 0; j < 8; j++)
        o[j][0] = o[j][1] = o[j][2] = o[j][3] = 0.f;
    float rsl = 0.f, rsh = 0.f;

    for (int t = 0; t <= qt; t++) {
        const int cur = t & 1, nxt = cur ^ 1;
        const bool hasNext = (t < qt);
        const uint32_t KHIc = smb + KBUF(cur);
        const uint32_t VHIc = smb + VBUF(cur);
        const int k0 = t * 128;
        const bool diag = (t == qt);
        const int kb = k0 + nhalf * 64 + 2 * (lane & 3);
        const bool skipw = diag && nhalf == 1 && mrow < 4;

        // prefetch next K tile into registers (hidden by h=0 compute)
        float4 kreg[4];
        if (hasNext) {
            const float* Kg = K + ((size_t)bh * SEQ + k0 + 128) * HD;
            #pragma unroll
            for (int it = 0; it < 4; it++) {
                int i = tid + it * 512;
                kreg[it] = *(const float4*)(Kg + (i >> 4) * HD + (i & 15) * 4);
            }
        }

        if (skipw) {
            #pragma unroll
            for (int jl2 = 0; jl2 < 8; jl2++) {
                int kc = kb + jl2 * 8;
                *(float2*)(E + ((size_t)bh * SEQ + qrl) * SEQ + kc) = make_float2(0.f, 0.f);
                *(float2*)(E + ((size_t)bh * SEQ + qrh) * SEQ + kc) = make_float2(0.f, 0.f);
            }
        }

        #pragma unroll
        for (int h = 0; h < 2; h++) {
            if (h == 1 && hasNext) {
                // convert K(t+1) into alternate planes; prefetch next V tile
                #pragma unroll
                for (int it = 0; it < 4; it++) {
                    int i = tid + it * 512;
                    int row = i >> 4, c4 = i & 15;
                    uint32_t off = SWZ(row * 128 + c4 * 8);
                    uint32_t h0, l0, h1, l1;
                    split2h(kreg[it].x, kreg[it].y, h0, l0);
                    split2h(kreg[it].z, kreg[it].w, h1, l1);
                    *(uint2*)(sm + KBUF(nxt)         + off) = make_uint2(h0, h1);
                    *(uint2*)(sm + KBUF(nxt) + 16384 + off) = make_uint2(l0, l1);
                    const float* Vg = V + ((size_t)bh * SEQ + k0 + 128) * HD;
                    kreg[it] = *(const float4*)(Vg + row * HD + c4 * 4);
                }
            }
            if (skipw) continue;

            float c[4][4];
            #pragma unroll
            for (int j = 0; j < 4; j++)
                c[j][0] = c[j][1] = c[j][2] = c[j][3] = 0.f;

            // ---- QK^T (fp16: Q single, K hi+lo) ----
            #pragma unroll
            for (int s = 0; s < 4; s++) {
                #pragma unroll
                for (int pp = 0; pp < 2; pp++) {
                    int p = 2 * h + pp;
                    uint32_t kh[4], kl[4];
                    uint32_t ax = ka[p] ^ (cbq + (s << 5));
                    ldsm4(kh, KHIc + ax);
                    ldsm4(kl, KHIc + 16384 + ax);
                    mma_f16(c[2 * pp],     qf[s], kl[0], kl[1]);
                    mma_f16(c[2 * pp],     qf[s], kh[0], kh[1]);
                    mma_f16(c[2 * pp + 1], qf[s], kl[2], kl[3]);
                    mma_f16(c[2 * pp + 1], qf[s], kh[2], kh[3]);
                }
            }

            // ---- mask + exp + rowsum + store E ----
            #pragma unroll
            for (int jl = 0; jl < 4; jl++) {
                int kc = kb + (4 * h + jl) * 8;
                c[jl][0] = (mql && (!diag || kc     + mn <= qrl)) ? __expf(c[jl][0]) : 0.f;
                c[jl][1] = (mql && (!diag || kc + 1 + mn <= qrl)) ? __expf(c[jl][1]) : 0.f;
                c[jl][2] = (mqh && (!diag || kc     + mn <= qrh)) ? __expf(c[jl][2]) : 0.f;
                c[jl][3] = (mqh && (!diag || kc + 1 + mn <= qrh)) ? __expf(c[jl][3]) : 0.f;
                rsl += c[jl][0] + c[jl][1];
                rsh += c[jl][2] + c[jl][3];
                *(float2*)(E + ((size_t)bh * SEQ + qrl) * SEQ + kc) =
                    make_float2(c[jl][0], c[jl][1]);
                *(float2*)(E + ((size_t)bh * SEQ + qrh) * SEQ + kc) =
                    make_float2(c[jl][2], c[jl][3]);
            }

            // ---- PV (fp16): A = E fp16, B = V fp16 hi+lo ----
            #pragma unroll
            for (int sl = 0; sl < 2; sl++) {
                int s = 2 * h + sl;
                uint32_t af[4];
                af[0] = pack2h(c[2 * sl][0],     c[2 * sl][1]);
                af[1] = pack2h(c[2 * sl][2],     c[2 * sl][3]);
                af[2] = pack2h(c[2 * sl + 1][0], c[2 * sl + 1][1]);
                af[3] = pack2h(c[2 * sl + 1][2], c[2 * sl + 1][3]);
                #pragma unroll
                for (int p = 0; p < 4; p++) {
                    uint32_t bhr[4], blr[4];
                    uint32_t ax = va[s] ^ (cbv + (p << 5));
                    ldsm4t(bhr, VHIc + ax);
                    ldsm4t(blr, VHIc + 16384 + ax);
                    mma_f16(o[2 * p],     af, blr[0], blr[1]);
                    mma_f16(o[2 * p],     af, bhr[0], bhr[1]);
                    mma_f16(o[2 * p + 1], af, blr[2], blr[3]);
                    mma_f16(o[2 * p + 1], af, bhr[2], bhr[3]);
                }
            }
        }

        // convert V(t+1) (staged in kreg) into alternate fp16 planes
        if (hasNext) {
            #pragma unroll
            for (int it = 0; it < 4; it++) {
                int i = tid + it * 512;
                int row = i >> 4, c4 = i & 15;
                uint32_t off = SWZ(row * 128 + c4 * 8);
                uint32_t h0, l0, h1, l1;
                split2h(kreg[it].x, kreg[it].y, h0, l0);
                split2h(kreg[it].z, kreg[it].w, h1, l1);
                *(uint2*)(sm + VBUF(nxt)         + off) = make_uint2(h0, h1);
                *(uint2*)(sm + VBUF(nxt) + 16384 + off) = make_uint2(l0, l1);
            }
        }
        __syncthreads();
    }

    // ---- rowsums -> l, inv ----
    rsl += __shfl_xor_sync(0xffffffffu, rsl, 1);
    rsl += __shfl_xor_sync(0xffffffffu, rsl, 2);
    rsh += __shfl_xor_sync(0xffffffffu, rsh, 1);
    rsh += __shfl_xor_sync(0xffffffffu, rsh, 2);
    if ((lane & 3) == 0) {
        RS[nhalf * 128 + rl] = rsl;
        RS[nhalf * 128 + rh] = rsh;
    }
    __syncthreads();
    if (tid < 128) {
        float l = RS[tid] + RS[128 + tid];
        g_l[bh * SEQ + q0 + tid] = l;
        INV[tid] = (l > 0.f) ? (1.f / l) : 0.f;
    }
    __syncthreads();

    // ---- cross-warp O reduce (+ scale) and store ----
    const int dcol = 2 * (lane & 3);
    if (nhalf == 1) {
        #pragma unroll
        for (int j = 0; j < 8; j++) {
            *(float2*)(Ob + rl * 68 + j * 8 + dcol) = make_float2(o[j][0], o[j][1]);
            *(float2*)(Ob + rh * 68 + j * 8 + dcol) = make_float2(o[j][2], o[j][3]);
        }
    }
    __syncthreads();
    if (nhalf == 0) {
        float il = INV[rl], ih = INV[rh];
        #pragma unroll
        for (int j = 0; j < 8; j++) {
            float2 p0 = *(float2*)(Ob + rl * 68 + j * 8 + dcol);
            float2 p1 = *(float2*)(Ob + rh * 68 + j * 8 + dcol);
            *(float2*)(O + ((size_t)bh * SEQ + qrl) * HD + j * 8 + dcol) =
                make_float2((o[j][0] + p0.x) * il, (o[j][1] + p0.y) * il);
            *(float2*)(O + ((size_t)bh * SEQ + qrh) * HD + j * 8 + dcol) =
                make_float2((o[j][2] + p1.x) * ih, (o[j][3] + p1.y) * ih);
        }
    }

    // ---- in-place normalization of this block's causal rows: P = E/l ----
    for (int r = warp; r < 128; r += 16) {
        const int q = q0 + r;
        const float inv = INV[r];
        const int nf4 = (q - mn + 4) >> 2;
        float4* rowp = (float4*)(E + ((size_t)bh * SEQ + q) * SEQ);
        for (int cc = lane; cc < nf4; cc += 32) {
            float4 v = rowp[cc];
            v.x *= inv; v.y *= inv; v.z *= inv; v.w *= inv;
            rowp[cc] = v;
        }
    }
}

// ---------------------------------------------------------------------------
extern "C" void kernel_launch(void* const* d_in, const int* in_sizes, int n_in,
                              void* d_out, int out_size)
{
    const float* Q        = (const float*)d_in[0];
    const float* K        = (const float*)d_in[1];
    const float* V        = (const float*)d_in[2];
    const float* mask     = (const float*)d_in[3];
    const int*   mask_now = (const int*)d_in[4];

    float* O = (float*)d_out;                      // [B,H,S,D]
    float* P = O + (size_t)NBH * SEQ * HD;         // [B,H,S,S]

    cudaFuncSetAttribute(k_attn, cudaFuncAttributeMaxDynamicSharedMemorySize, 148992);

    k_attn<<<dim3(16, NBH), 512, 148992>>>(Q, K, V, mask, mask_now, P, O);
}

// round 8
// speedup vs baseline: 1.5683x; 1.0934x over previous
#include <cuda_runtime.h>
#include <cuda_bf16.h>
#include <cuda_fp16.h>
#include <cstdint>

#define SEQ 2048
#define HD  64
#define NBH 32

__device__ float g_l[NBH * SEQ];

#define SWZ(x) ((x) ^ (((x) >> 3) & 0x70))

__device__ __forceinline__ uint32_t smem_u32(const void* p) {
    uint32_t a;
    asm("{ .reg .u64 t; cvta.to.shared.u64 t, %1; cvt.u32.u64 %0, t; }"
        : "=r"(a) : "l"(p));
    return a;
}
__device__ __forceinline__ void ldsm4(uint32_t* d, uint32_t a) {
    asm volatile("ldmatrix.sync.aligned.m8n8.x4.shared.b16 {%0,%1,%2,%3}, [%4];"
        : "=r"(d[0]), "=r"(d[1]), "=r"(d[2]), "=r"(d[3]) : "r"(a));
}
__device__ __forceinline__ void ldsm4t(uint32_t* d, uint32_t a) {
    asm volatile("ldmatrix.sync.aligned.m8n8.x4.trans.shared.b16 {%0,%1,%2,%3}, [%4];"
        : "=r"(d[0]), "=r"(d[1]), "=r"(d[2]), "=r"(d[3]) : "r"(a));
}
__device__ __forceinline__ void mma_f16(float* c, const uint32_t* a,
                                        uint32_t b0, uint32_t b1) {
    asm volatile(
        "mma.sync.aligned.m16n8k16.row.col.f32.f16.f16.f32 "
        "{%0,%1,%2,%3}, {%4,%5,%6,%7}, {%8,%9}, {%0,%1,%2,%3};"
        : "+f"(c[0]), "+f"(c[1]), "+f"(c[2]), "+f"(c[3])
        : "r"(a[0]), "r"(a[1]), "r"(a[2]), "r"(a[3]), "r"(b0), "r"(b1));
}
// fp32 pair -> packed fp16 hi word + residual lo word
__device__ __forceinline__ void split2h(float x0, float x1, uint32_t& hi, uint32_t& lo) {
    __half2 h = __floats2half2_rn(x0, x1);
    float2 hf = __half22float2(h);
    __half2 l = __floats2half2_rn(x0 - hf.x, x1 - hf.y);
    hi = *reinterpret_cast<uint32_t*>(&h);
    lo = *reinterpret_cast<uint32_t*>(&l);
}
__device__ __forceinline__ uint32_t pack2h(float x0, float x1) {
    __half2 h = __floats2half2_rn(x0, x1);
    return *reinterpret_cast<uint32_t*>(&h);
}
// swizzled base for row r (128B rows): SWZ(lin) == swzrow(r) ^ (ch*16)
__device__ __forceinline__ uint32_t swzrow(int r) {
    uint32_t x = (uint32_t)r << 7;
    return x ^ ((x >> 3) & 0x70);
}

// smem map (bytes):
//  QF  0..16K                             (fp16 plane, persistent)
//  K buf b: 16384 + b*16384               (fp16 single, double-buffered) 16K..48K
//  V buf b: 49152 + b*32768 hi, +16384 lo (fp16 hi+lo, double-buffered)  48K..112K
//  RS 114688 (1KB), INV 115712 (512B); total 116224
//  Ob reuses 16384.. after mainloop
#define KBUF(b) (16384u + (b) * 16384u)
#define VBUF(b) (49152u + (b) * 32768u)

__global__ __launch_bounds__(512, 1) void k_attn(
    const float* __restrict__ Q, const float* __restrict__ K,
    const float* __restrict__ V, const float* __restrict__ mask,
    const int* __restrict__ mask_now,
    float* __restrict__ E, float* __restrict__ O)
{
    extern __shared__ char sm[];
    const uint32_t smb = smem_u32(sm);
    const int tid = threadIdx.x, lane = tid & 31, warp = tid >> 5;
    const int mrow = warp >> 1, nhalf = warp & 1;
    const int g = lane >> 3, r8 = lane & 7;
    const int qt = 15 - blockIdx.x, bh = blockIdx.y, b = bh >> 4;
    const int q0 = qt * 128;
    const int mn = mask_now[0];

    float* RS  = (float*)(sm + 114688);
    float* INV = (float*)(sm + 115712);
    float* Ob  = (float*)(sm + 16384);

    // ---- stage Q plane (pre-scaled by 1/8) + tile-0 K/V planes ----
    {
        const float* Qg = Q + ((size_t)bh * SEQ + q0) * HD;
        const float* Kg = K + (size_t)bh * SEQ * HD;
        const float* Vg = V + (size_t)bh * SEQ * HD;
        #pragma unroll
        for (int it = 0; it < 4; it++) {
            int i = tid + it * 512;
            int row = i >> 4, c4 = i & 15;
            uint32_t off = SWZ(row * 128 + c4 * 8);
            uint32_t h0, l0, h1, l1;
            float4 v = *(const float4*)(Qg + row * HD + c4 * 4);
            *(uint2*)(sm + 0 + off) = make_uint2(
                pack2h(v.x * 0.125f, v.y * 0.125f),
                pack2h(v.z * 0.125f, v.w * 0.125f));
            v = *(const float4*)(Kg + row * HD + c4 * 4);
            *(uint2*)(sm + KBUF(0) + off) = make_uint2(
                pack2h(v.x, v.y), pack2h(v.z, v.w));
            v = *(const float4*)(Vg + row * HD + c4 * 4);
            split2h(v.x, v.y, h0, l0); split2h(v.z, v.w, h1, l1);
            *(uint2*)(sm + VBUF(0)         + off) = make_uint2(h0, h1);
            *(uint2*)(sm + VBUF(0) + 16384 + off) = make_uint2(l0, l1);
        }
    }

    // zero-fill E cols [q0+128, SEQ)
    {
        const int c0 = q0 + 128;
        const int w = (SEQ - c0) >> 2;
        for (int r = warp; r < 128; r += 16) {
            float4* rowp = (float4*)(E + ((size_t)bh * SEQ + q0 + r) * SEQ + c0);
            for (int cc = lane; cc < w; cc += 32)
                rowp[cc] = make_float4(0.f, 0.f, 0.f, 0.f);
        }
    }

    const int rl = mrow * 16 + (lane >> 2), rh = rl + 8;
    const int qrl = q0 + rl, qrh = q0 + rh;
    const bool mql = mask[(size_t)b * SEQ + qrl] != 0.f;
    const bool mqh = mask[(size_t)b * SEQ + qrh] != 0.f;

    // precomputed swizzled ldsm row-bases
    const uint32_t cbq = (uint32_t)(lane & 8) << 1;         // (g&1)*16
    const uint32_t cbv = (uint32_t)(g >> 1) << 4;           // (g>>1)*16
    uint32_t ka[4], va[4];
    #pragma unroll
    for (int p = 0; p < 4; p++)
        ka[p] = swzrow(nhalf * 64 + p * 16 + ((g >> 1) << 3) + r8);
    #pragma unroll
    for (int s = 0; s < 4; s++)
        va[s] = swzrow(nhalf * 64 + s * 16 + ((g & 1) << 3) + r8);
    const uint32_t qrowswz = swzrow(mrow * 16 + ((g & 1) << 3) + r8);

    __syncthreads();

    // hoist Q fragments (fp16, persistent plane)
    uint32_t qf[4][4];
    #pragma unroll
    for (int s = 0; s < 4; s++)
        ldsm4(qf[s], smb + (qrowswz ^ (cbv + (s << 5))));

    float o[8][4];
    #pragma unroll
    for (int j = 0; j < 8; j++)
        o[j][0] = o[j][1] = o[j][2] = o[j][3] = 0.f;
    float rsl = 0.f, rsh = 0.f;

    for (int t = 0; t <= qt; t++) {
        const int cur = t & 1, nxt = cur ^ 1;
        const bool hasNext = (t < qt);
        const uint32_t Kc = smb + KBUF(cur);
        const uint32_t Vc = smb + VBUF(cur);
        const int k0 = t * 128;
        const bool diag = (t == qt);
        const int kb = k0 + nhalf * 64 + 2 * (lane & 3);
        const bool skipw = diag && nhalf == 1 && mrow < 4;

        // prefetch next K tile into registers (hidden by h=0 compute)
        float4 kreg[4];
        if (hasNext) {
            const float* Kg = K + ((size_t)bh * SEQ + k0 + 128) * HD;
            #pragma unroll
            for (int it = 0; it < 4; it++) {
                int i = tid + it * 512;
                kreg[it] = *(const float4*)(Kg + (i >> 4) * HD + (i & 15) * 4);
            }
        }

        if (skipw) {
            #pragma unroll
            for (int jl2 = 0; jl2 < 8; jl2++) {
                int kc = kb + jl2 * 8;
                *(float2*)(E + ((size_t)bh * SEQ + qrl) * SEQ + kc) = make_float2(0.f, 0.f);
                *(float2*)(E + ((size_t)bh * SEQ + qrh) * SEQ + kc) = make_float2(0.f, 0.f);
            }
        }

        #pragma unroll
        for (int h = 0; h < 2; h++) {
            if (h == 1 && hasNext) {
                // convert K(t+1) into alternate plane; prefetch next V tile
                #pragma unroll
                for (int it = 0; it < 4; it++) {
                    int i = tid + it * 512;
                    int row = i >> 4, c4 = i & 15;
                    uint32_t off = SWZ(row * 128 + c4 * 8);
                    *(uint2*)(sm + KBUF(nxt) + off) = make_uint2(
                        pack2h(kreg[it].x, kreg[it].y),
                        pack2h(kreg[it].z, kreg[it].w));
                    const float* Vg = V + ((size_t)bh * SEQ + k0 + 128) * HD;
                    kreg[it] = *(const float4*)(Vg + row * HD + c4 * 4);
                }
            }
            if (skipw) continue;

            float c[4][4];
            #pragma unroll
            for (int j = 0; j < 4; j++)
                c[j][0] = c[j][1] = c[j][2] = c[j][3] = 0.f;

            // ---- QK^T (fp16 single x single) ----
            #pragma unroll
            for (int s = 0; s < 4; s++) {
                #pragma unroll
                for (int pp = 0; pp < 2; pp++) {
                    int p = 2 * h + pp;
                    uint32_t kh[4];
                    ldsm4(kh, Kc + (ka[p] ^ (cbq + (s << 5))));
                    mma_f16(c[2 * pp],     qf[s], kh[0], kh[1]);
                    mma_f16(c[2 * pp + 1], qf[s], kh[2], kh[3]);
                }
            }

            // ---- mask + exp + rowsum + store E ----
            #pragma unroll
            for (int jl = 0; jl < 4; jl++) {
                int kc = kb + (4 * h + jl) * 8;
                c[jl][0] = (mql && (!diag || kc     + mn <= qrl)) ? __expf(c[jl][0]) : 0.f;
                c[jl][1] = (mql && (!diag || kc + 1 + mn <= qrl)) ? __expf(c[jl][1]) : 0.f;
                c[jl][2] = (mqh && (!diag || kc     + mn <= qrh)) ? __expf(c[jl][2]) : 0.f;
                c[jl][3] = (mqh && (!diag || kc + 1 + mn <= qrh)) ? __expf(c[jl][3]) : 0.f;
                rsl += c[jl][0] + c[jl][1];
                rsh += c[jl][2] + c[jl][3];
                *(float2*)(E + ((size_t)bh * SEQ + qrl) * SEQ + kc) =
                    make_float2(c[jl][0], c[jl][1]);
                *(float2*)(E + ((size_t)bh * SEQ + qrh) * SEQ + kc) =
                    make_float2(c[jl][2], c[jl][3]);
            }

            // ---- PV (fp16): A = E fp16, B = V fp16 hi+lo ----
            #pragma unroll
            for (int sl = 0; sl < 2; sl++) {
                int s = 2 * h + sl;
                uint32_t af[4];
                af[0] = pack2h(c[2 * sl][0],     c[2 * sl][1]);
                af[1] = pack2h(c[2 * sl][2],     c[2 * sl][3]);
                af[2] = pack2h(c[2 * sl + 1][0], c[2 * sl + 1][1]);
                af[3] = pack2h(c[2 * sl + 1][2], c[2 * sl + 1][3]);
                #pragma unroll
                for (int p = 0; p < 4; p++) {
                    uint32_t bhr[4], blr[4];
                    uint32_t ax = va[s] ^ (cbv + (p << 5));
                    ldsm4t(bhr, Vc + ax);
                    ldsm4t(blr, Vc + 16384 + ax);
                    mma_f16(o[2 * p],     af, blr[0], blr[1]);
                    mma_f16(o[2 * p],     af, bhr[0], bhr[1]);
                    mma_f16(o[2 * p + 1], af, blr[2], blr[3]);
                    mma_f16(o[2 * p + 1], af, bhr[2], bhr[3]);
                }
            }
        }

        // convert V(t+1) (staged in kreg) into alternate fp16 planes
        if (hasNext) {
            #pragma unroll
            for (int it = 0; it < 4; it++) {
                int i = tid + it * 512;
                int row = i >> 4, c4 = i & 15;
                uint32_t off = SWZ(row * 128 + c4 * 8);
                uint32_t h0, l0, h1, l1;
                split2h(kreg[it].x, kreg[it].y, h0, l0);
                split2h(kreg[it].z, kreg[it].w, h1, l1);
                *(uint2*)(sm + VBUF(nxt)         + off) = make_uint2(h0, h1);
                *(uint2*)(sm + VBUF(nxt) + 16384 + off) = make_uint2(l0, l1);
            }
        }
        __syncthreads();
    }

    // ---- rowsums -> l, inv ----
    rsl += __shfl_xor_sync(0xffffffffu, rsl, 1);
    rsl += __shfl_xor_sync(0xffffffffu, rsl, 2);
    rsh += __shfl_xor_sync(0xffffffffu, rsh, 1);
    rsh += __shfl_xor_sync(0xffffffffu, rsh, 2);
    if ((lane & 3) == 0) {
        RS[nhalf * 128 + rl] = rsl;
        RS[nhalf * 128 + rh] = rsh;
    }
    __syncthreads();
    if (tid < 128) {
        float l = RS[tid] + RS[128 + tid];
        g_l[bh * SEQ + q0 + tid] = l;
        INV[tid] = (l > 0.f) ? (1.f / l) : 0.f;
    }
    __syncthreads();

    // ---- cross-warp O reduce (+ scale) and store ----
    const int dcol = 2 * (lane & 3);
    if (nhalf == 1) {
        #pragma unroll
        for (int j = 0; j < 8; j++) {
            *(float2*)(Ob + rl * 68 + j * 8 + dcol) = make_float2(o[j][0], o[j][1]);
            *(float2*)(Ob + rh * 68 + j * 8 + dcol) = make_float2(o[j][2], o[j][3]);
        }
    }
    __syncthreads();
    if (nhalf == 0) {
        float il = INV[rl], ih = INV[rh];
        #pragma unroll
        for (int j = 0; j < 8; j++) {
            float2 p0 = *(float2*)(Ob + rl * 68 + j * 8 + dcol);
            float2 p1 = *(float2*)(Ob + rh * 68 + j * 8 + dcol);
            *(float2*)(O + ((size_t)bh * SEQ + qrl) * HD + j * 8 + dcol) =
                make_float2((o[j][0] + p0.x) * il, (o[j][1] + p0.y) * il);
            *(float2*)(O + ((size_t)bh * SEQ + qrh) * HD + j * 8 + dcol) =
                make_float2((o[j][2] + p1.x) * ih, (o[j][3] + p1.y) * ih);
        }
    }

    // ---- in-place normalization of this block's causal rows: P = E/l ----
    for (int r = warp; r < 128; r += 16) {
        const int q = q0 + r;
        const float inv = INV[r];
        const int nf4 = (q - mn + 4) >> 2;
        float4* rowp = (float4*)(E + ((size_t)bh * SEQ + q) * SEQ);
        for (int cc = lane; cc < nf4; cc += 32) {
            float4 v = rowp[cc];
            v.x *= inv; v.y *= inv; v.z *= inv; v.w *= inv;
            rowp[cc] = v;
        }
    }
}

// ---------------------------------------------------------------------------
extern "C" void kernel_launch(void* const* d_in, const int* in_sizes, int n_in,
                              void* d_out, int out_size)
{
    const float* Q        = (const float*)d_in[0];
    const float* K        = (const float*)d_in[1];
    const float* V        = (const float*)d_in[2];
    const float* mask     = (const float*)d_in[3];
    const int*   mask_now = (const int*)d_in[4];

    float* O = (float*)d_out;                      // [B,H,S,D]
    float* P = O + (size_t)NBH * SEQ * HD;         // [B,H,S,S]

    cudaFuncSetAttribute(k_attn, cudaFuncAttributeMaxDynamicSharedMemorySize, 116224);

    k_attn<<<dim3(16, NBH), 512, 116224>>>(Q, K, V, mask, mask_now, P, O);
}

// round 9
// speedup vs baseline: 1.6502x; 1.0522x over previous
#include <cuda_runtime.h>
#include <cuda_fp16.h>
#include <cstdint>

#define SEQ 2048
#define HD  64
#define NBH 32

#define SWZ(x) ((x) ^ (((x) >> 3) & 0x70))

__device__ __forceinline__ uint32_t smem_u32(const void* p) {
    uint32_t a;
    asm("{ .reg .u64 t; cvta.to.shared.u64 t, %1; cvt.u32.u64 %0, t; }"
        : "=r"(a) : "l"(p));
    return a;
}
__device__ __forceinline__ void ldsm4(uint32_t* d, uint32_t a) {
    asm volatile("ldmatrix.sync.aligned.m8n8.x4.shared.b16 {%0,%1,%2,%3}, [%4];"
        : "=r"(d[0]), "=r"(d[1]), "=r"(d[2]), "=r"(d[3]) : "r"(a));
}
__device__ __forceinline__ void ldsm4t(uint32_t* d, uint32_t a) {
    asm volatile("ldmatrix.sync.aligned.m8n8.x4.trans.shared.b16 {%0,%1,%2,%3}, [%4];"
        : "=r"(d[0]), "=r"(d[1]), "=r"(d[2]), "=r"(d[3]) : "r"(a));
}
__device__ __forceinline__ void mma_f16(float* c, const uint32_t* a,
                                        uint32_t b0, uint32_t b1) {
    asm volatile(
        "mma.sync.aligned.m16n8k16.row.col.f32.f16.f16.f32 "
        "{%0,%1,%2,%3}, {%4,%5,%6,%7}, {%8,%9}, {%0,%1,%2,%3};"
        : "+f"(c[0]), "+f"(c[1]), "+f"(c[2]), "+f"(c[3])
        : "r"(a[0]), "r"(a[1]), "r"(a[2]), "r"(a[3]), "r"(b0), "r"(b1));
}
__device__ __forceinline__ uint32_t pack2h(float x0, float x1) {
    __half2 h = __floats2half2_rn(x0, x1);
    return *reinterpret_cast<uint32_t*>(&h);
}
// swizzled base for row r (128B rows): SWZ(r*128 + ch*16) == swzrow(r) ^ (ch*16)
__device__ __forceinline__ uint32_t swzrow(int r) {
    uint32_t x = (uint32_t)r << 7;
    return x ^ ((x >> 3) & 0x70);
}

// smem map (bytes): QF 0..16K (fp16, persistent)
//  K buf b: 16384 + b*16384 (fp16 single, dbuf)   16K..48K
//  V buf b: 49152 + b*16384 (fp16 single, dbuf)   48K..80K
//  INV @81920 (512B); total 82432
#define KBUF(b) (16384u + (b) * 16384u)
#define VBUF(b) (49152u + (b) * 16384u)

__global__ __launch_bounds__(256, 2) void k_attn(
    const float* __restrict__ Q, const float* __restrict__ K,
    const float* __restrict__ V, const float* __restrict__ mask,
    const int* __restrict__ mask_now,
    float* __restrict__ E, float* __restrict__ O)
{
    extern __shared__ char sm[];
    const uint32_t smb = smem_u32(sm);
    const int tid = threadIdx.x, lane = tid & 31, warp = tid >> 5;  // warp = mrow
    const int g = lane >> 3, r8 = lane & 7;
    const int qt = 15 - blockIdx.x, bh = blockIdx.y, b = bh >> 4;
    const int q0 = qt * 128;
    const int mn = mask_now[0];

    float* INV = (float*)(sm + 81920);

    // ---- stage Q (pre-scaled by 1/8) + tile-0 K/V fp16 planes ----
    {
        const float* Qg = Q + ((size_t)bh * SEQ + q0) * HD;
        const float* Kg = K + (size_t)bh * SEQ * HD;
        const float* Vg = V + (size_t)bh * SEQ * HD;
        #pragma unroll
        for (int it = 0; it < 8; it++) {
            int i = tid + it * 256;
            int row = i >> 4, c4 = i & 15;
            uint32_t off = SWZ(row * 128 + c4 * 8);
            float4 v = *(const float4*)(Qg + row * HD + c4 * 4);
            *(uint2*)(sm + 0 + off) = make_uint2(
                pack2h(v.x * 0.125f, v.y * 0.125f),
                pack2h(v.z * 0.125f, v.w * 0.125f));
            v = *(const float4*)(Kg + row * HD + c4 * 4);
            *(uint2*)(sm + KBUF(0) + off) = make_uint2(
                pack2h(v.x, v.y), pack2h(v.z, v.w));
            v = *(const float4*)(Vg + row * HD + c4 * 4);
            *(uint2*)(sm + VBUF(0) + off) = make_uint2(
                pack2h(v.x, v.y), pack2h(v.z, v.w));
        }
    }

    // zero-fill E cols [q0+128, SEQ)
    {
        const int c0 = q0 + 128;
        const int w = (SEQ - c0) >> 2;
        for (int r = warp; r < 128; r += 8) {
            float4* rowp = (float4*)(E + ((size_t)bh * SEQ + q0 + r) * SEQ + c0);
            for (int cc = lane; cc < w; cc += 32)
                rowp[cc] = make_float4(0.f, 0.f, 0.f, 0.f);
        }
    }

    const int rl = warp * 16 + (lane >> 2), rh = rl + 8;
    const int qrl = q0 + rl, qrh = q0 + rh;
    const bool mql = mask[(size_t)b * SEQ + qrl] != 0.f;
    const bool mqh = mask[(size_t)b * SEQ + qrh] != 0.f;

    // swizzled ldsm bases
    const uint32_t cbq = (uint32_t)(lane & 8) << 1;        // (g&1)*16
    const uint32_t cbv = (uint32_t)(g >> 1) << 4;          // (g>>1)*16
    const uint32_t ka0 = swzrow(((g >> 1) << 3) + r8);     // K rows, +kg*2048
    const uint32_t va0 = swzrow(((g & 1) << 3) + r8);      // V rows, +kg*2048
    const uint32_t qrowswz = swzrow(warp * 16 + ((g & 1) << 3) + r8);

    __syncthreads();

    // hoist Q fragments
    uint32_t qf[4][4];
    #pragma unroll
    for (int s = 0; s < 4; s++)
        ldsm4(qf[s], smb + (qrowswz ^ (cbv | (s << 5))));

    float o[8][4];
    #pragma unroll
    for (int j = 0; j < 8; j++)
        o[j][0] = o[j][1] = o[j][2] = o[j][3] = 0.f;
    float rsl = 0.f, rsh = 0.f;

    for (int t = 0; t <= qt; t++) {
        const int cur = t & 1, nxt = cur ^ 1;
        const bool hasNext = (t < qt);
        const uint32_t Kc = smb + KBUF(cur);
        const uint32_t Vc = smb + VBUF(cur);
        const int k0 = t * 128;
        const bool diag = (t == qt);
        const float* Kg = K + ((size_t)bh * SEQ + k0 + 128) * HD;
        const float* Vg = V + ((size_t)bh * SEQ + k0 + 128) * HD;

        #pragma unroll
        for (int h = 0; h < 4; h++) {
            // prefetch next-tile slices (2/8 of K and V each chunk)
            float4 pk[2], pv[2];
            if (hasNext) {
                #pragma unroll
                for (int u = 0; u < 2; u++) {
                    int i = tid + (2 * h + u) * 256;
                    pk[u] = *(const float4*)(Kg + (i >> 4) * HD + (i & 15) * 4);
                    pv[u] = *(const float4*)(Vg + (i >> 4) * HD + (i & 15) * 4);
                }
            }

            const bool skipc = diag && (2 * h > warp);
            if (skipc) {
                #pragma unroll
                for (int jl = 0; jl < 4; jl++) {
                    int kc = k0 + h * 32 + jl * 8 + 2 * (lane & 3);
                    *(float2*)(E + ((size_t)bh * SEQ + qrl) * SEQ + kc) = make_float2(0.f, 0.f);
                    *(float2*)(E + ((size_t)bh * SEQ + qrh) * SEQ + kc) = make_float2(0.f, 0.f);
                }
            } else {
                float c[4][4];
                #pragma unroll
                for (int j = 0; j < 4; j++)
                    c[j][0] = c[j][1] = c[j][2] = c[j][3] = 0.f;

                // ---- QK^T chunk (cols [k0+h*32, +32)) ----
                #pragma unroll
                for (int s = 0; s < 4; s++) {
                    #pragma unroll
                    for (int pp = 0; pp < 2; pp++) {
                        uint32_t kh[4];
                        uint32_t addr = Kc +
                            ((ka0 + ((uint32_t)(2 * h + pp) << 11)) ^ (cbq | (s << 5)));
                        ldsm4(kh, addr);
                        mma_f16(c[2 * pp],     qf[s], kh[0], kh[1]);
                        mma_f16(c[2 * pp + 1], qf[s], kh[2], kh[3]);
                    }
                }

                // ---- mask + exp + rowsum + store E ----
                #pragma unroll
                for (int jl = 0; jl < 4; jl++) {
                    int kc = k0 + h * 32 + jl * 8 + 2 * (lane & 3);
                    c[jl][0] = (mql && (!diag || kc     + mn <= qrl)) ? __expf(c[jl][0]) : 0.f;
                    c[jl][1] = (mql && (!diag || kc + 1 + mn <= qrl)) ? __expf(c[jl][1]) : 0.f;
                    c[jl][2] = (mqh && (!diag || kc     + mn <= qrh)) ? __expf(c[jl][2]) : 0.f;
                    c[jl][3] = (mqh && (!diag || kc + 1 + mn <= qrh)) ? __expf(c[jl][3]) : 0.f;
                    rsl += c[jl][0] + c[jl][1];
                    rsh += c[jl][2] + c[jl][3];
                    *(float2*)(E + ((size_t)bh * SEQ + qrl) * SEQ + kc) =
                        make_float2(c[jl][0], c[jl][1]);
                    *(float2*)(E + ((size_t)bh * SEQ + qrh) * SEQ + kc) =
                        make_float2(c[jl][2], c[jl][3]);
                }

                // ---- PV chunk: A = E fp16 (regs), B = V fp16 ----
                #pragma unroll
                for (int sl = 0; sl < 2; sl++) {
                    uint32_t af[4];
                    af[0] = pack2h(c[2 * sl][0],     c[2 * sl][1]);
                    af[1] = pack2h(c[2 * sl][2],     c[2 * sl][3]);
                    af[2] = pack2h(c[2 * sl + 1][0], c[2 * sl + 1][1]);
                    af[3] = pack2h(c[2 * sl + 1][2], c[2 * sl + 1][3]);
                    uint32_t vrow = va0 + ((uint32_t)(2 * h + sl) << 11);
                    #pragma unroll
                    for (int p = 0; p < 4; p++) {
                        uint32_t bhr[4];
                        ldsm4t(bhr, Vc + (vrow ^ (cbv | (p << 5))));
                        mma_f16(o[2 * p],     af, bhr[0], bhr[1]);
                        mma_f16(o[2 * p + 1], af, bhr[2], bhr[3]);
                    }
                }
            }

            // convert + store prefetched slices (dbuf targets, no sync needed)
            if (hasNext) {
                #pragma unroll
                for (int u = 0; u < 2; u++) {
                    int i = tid + (2 * h + u) * 256;
                    int row = i >> 4, c4 = i & 15;
                    uint32_t off = SWZ(row * 128 + c4 * 8);
                    *(uint2*)(sm + KBUF(nxt) + off) = make_uint2(
                        pack2h(pk[u].x, pk[u].y), pack2h(pk[u].z, pk[u].w));
                    *(uint2*)(sm + VBUF(nxt) + off) = make_uint2(
                        pack2h(pv[u].x, pv[u].y), pack2h(pv[u].z, pv[u].w));
                }
            }
        }
        __syncthreads();
    }

    // ---- rowsums complete in-warp ----
    rsl += __shfl_xor_sync(0xffffffffu, rsl, 1);
    rsl += __shfl_xor_sync(0xffffffffu, rsl, 2);
    rsh += __shfl_xor_sync(0xffffffffu, rsh, 1);
    rsh += __shfl_xor_sync(0xffffffffu, rsh, 2);
    const float il = (rsl > 0.f) ? (1.f / rsl) : 0.f;
    const float ih = (rsh > 0.f) ? (1.f / rsh) : 0.f;
    if ((lane & 3) == 0) { INV[rl] = il; INV[rh] = ih; }

    // ---- O store (scaled), no cross-warp reduce needed ----
    const int dcol = 2 * (lane & 3);
    #pragma unroll
    for (int j = 0; j < 8; j++) {
        *(float2*)(O + ((size_t)bh * SEQ + qrl) * HD + j * 8 + dcol) =
            make_float2(o[j][0] * il, o[j][1] * il);
        *(float2*)(O + ((size_t)bh * SEQ + qrh) * HD + j * 8 + dcol) =
            make_float2(o[j][2] * ih, o[j][3] * ih);
    }
    __syncthreads();

    // ---- in-place normalization of causal rows: P = E/l ----
    for (int r = warp; r < 128; r += 8) {
        const int q = q0 + r;
        const float inv = INV[r];
        const int nf4 = (q - mn + 4) >> 2;
        float4* rowp = (float4*)(E + ((size_t)bh * SEQ + q) * SEQ);
        for (int cc = lane; cc < nf4; cc += 32) {
            float4 v = rowp[cc];
            v.x *= inv; v.y *= inv; v.z *= inv; v.w *= inv;
            rowp[cc] = v;
        }
    }
}

// ---------------------------------------------------------------------------
extern "C" void kernel_launch(void* const* d_in, const int* in_sizes, int n_in,
                              void* d_out, int out_size)
{
    const float* Q        = (const float*)d_in[0];
    const float* K        = (const float*)d_in[1];
    const float* V        = (const float*)d_in[2];
    const float* mask     = (const float*)d_in[3];
    const int*   mask_now = (const int*)d_in[4];

    float* O = (float*)d_out;                      // [B,H,S,D]
    float* P = O + (size_t)NBH * SEQ * HD;         // [B,H,S,S]

    cudaFuncSetAttribute(k_attn, cudaFuncAttributeMaxDynamicSharedMemorySize, 82432);

    k_attn<<<dim3(16, NBH), 256, 82432>>>(Q, K, V, mask, mask_now, P, O);
}

// round 10
// speedup vs baseline: 1.8476x; 1.1196x over previous
#include <cuda_runtime.h>
#include <cuda_fp16.h>
#include <cstdint>

#define SEQ 2048
#define HD  64
#define NBH 32

#define SWZ(x) ((x) ^ (((x) >> 3) & 0x70))

__device__ __forceinline__ uint32_t smem_u32(const void* p) {
    uint32_t a;
    asm("{ .reg .u64 t; cvta.to.shared.u64 t, %1; cvt.u32.u64 %0, t; }"
        : "=r"(a) : "l"(p));
    return a;
}
__device__ __forceinline__ void ldsm4(uint32_t* d, uint32_t a) {
    asm volatile("ldmatrix.sync.aligned.m8n8.x4.shared.b16 {%0,%1,%2,%3}, [%4];"
        : "=r"(d[0]), "=r"(d[1]), "=r"(d[2]), "=r"(d[3]) : "r"(a));
}
__device__ __forceinline__ void ldsm4t(uint32_t* d, uint32_t a) {
    asm volatile("ldmatrix.sync.aligned.m8n8.x4.trans.shared.b16 {%0,%1,%2,%3}, [%4];"
        : "=r"(d[0]), "=r"(d[1]), "=r"(d[2]), "=r"(d[3]) : "r"(a));
}
__device__ __forceinline__ void mma_f16(float* c, const uint32_t* a,
                                        uint32_t b0, uint32_t b1) {
    asm volatile(
        "mma.sync.aligned.m16n8k16.row.col.f32.f16.f16.f32 "
        "{%0,%1,%2,%3}, {%4,%5,%6,%7}, {%8,%9}, {%0,%1,%2,%3};"
        : "+f"(c[0]), "+f"(c[1]), "+f"(c[2]), "+f"(c[3])
        : "r"(a[0]), "r"(a[1]), "r"(a[2]), "r"(a[3]), "r"(b0), "r"(b1));
}
__device__ __forceinline__ uint32_t pack2h(float x0, float x1) {
    __half2 h = __floats2half2_rn(x0, x1);
    return *reinterpret_cast<uint32_t*>(&h);
}
// swizzled base for row r (128B rows): SWZ(r*128 + ch*16) == swzrow(r) ^ (ch*16)
__device__ __forceinline__ uint32_t swzrow(int r) {
    uint32_t x = (uint32_t)r << 7;
    return x ^ ((x >> 3) & 0x70);
}

// smem map (bytes): QF 0..16K (fp16, persistent)
//  K buf b: 16384 + b*16384 (fp16, dbuf)   16K..48K   (used by both phases)
//  V buf b: 49152 + b*16384 (fp16, dbuf)   48K..80K   (phase 1 only)
//  INV @81920 (512B); total 82432
#define KBUF(b) (16384u + (b) * 16384u)
#define VBUF(b) (49152u + (b) * 16384u)

__global__ __launch_bounds__(256, 2) void k_attn(
    const float* __restrict__ Q, const float* __restrict__ K,
    const float* __restrict__ V, const float* __restrict__ mask,
    const int* __restrict__ mask_now,
    float* __restrict__ P, float* __restrict__ O)
{
    extern __shared__ char sm[];
    const uint32_t smb = smem_u32(sm);
    const int tid = threadIdx.x, lane = tid & 31, warp = tid >> 5;
    const int g = lane >> 3, r8 = lane & 7;
    const int qt = 15 - blockIdx.x, bh = blockIdx.y, b = bh >> 4;
    const int q0 = qt * 128;
    const int mn = mask_now[0];

    float* INV = (float*)(sm + 81920);

    // ---- stage Q (pre-scaled by 1/8) + tile-0 K/V fp16 planes ----
    {
        const float* Qg = Q + ((size_t)bh * SEQ + q0) * HD;
        const float* Kg = K + (size_t)bh * SEQ * HD;
        const float* Vg = V + (size_t)bh * SEQ * HD;
        #pragma unroll
        for (int it = 0; it < 8; it++) {
            int i = tid + it * 256;
            int row = i >> 4, c4 = i & 15;
            uint32_t off = SWZ(row * 128 + c4 * 8);
            float4 v = *(const float4*)(Qg + row * HD + c4 * 4);
            *(uint2*)(sm + 0 + off) = make_uint2(
                pack2h(v.x * 0.125f, v.y * 0.125f),
                pack2h(v.z * 0.125f, v.w * 0.125f));
            v = *(const float4*)(Kg + row * HD + c4 * 4);
            *(uint2*)(sm + KBUF(0) + off) = make_uint2(
                pack2h(v.x, v.y), pack2h(v.z, v.w));
            v = *(const float4*)(Vg + row * HD + c4 * 4);
            *(uint2*)(sm + VBUF(0) + off) = make_uint2(
                pack2h(v.x, v.y), pack2h(v.z, v.w));
        }
    }

    // zero-fill P cols [q0+128, SEQ) (overlaps phase-1 compute via other warps)
    {
        const int c0 = q0 + 128;
        const int w = (SEQ - c0) >> 2;
        for (int r = warp; r < 128; r += 8) {
            float4* rowp = (float4*)(P + ((size_t)bh * SEQ + q0 + r) * SEQ + c0);
            for (int cc = lane; cc < w; cc += 32)
                rowp[cc] = make_float4(0.f, 0.f, 0.f, 0.f);
        }
    }

    const int rl = warp * 16 + (lane >> 2), rh = rl + 8;
    const int qrl = q0 + rl, qrh = q0 + rh;
    const bool mql = mask[(size_t)b * SEQ + qrl] != 0.f;
    const bool mqh = mask[(size_t)b * SEQ + qrh] != 0.f;

    // swizzled ldsm bases
    const uint32_t cbq = (uint32_t)(lane & 8) << 1;        // (g&1)*16
    const uint32_t cbv = (uint32_t)(g >> 1) << 4;          // (g>>1)*16
    const uint32_t ka0 = swzrow(((g >> 1) << 3) + r8);
    const uint32_t va0 = swzrow(((g & 1) << 3) + r8);
    const uint32_t qrowswz = swzrow(warp * 16 + ((g & 1) << 3) + r8);

    __syncthreads();

    // hoist Q fragments
    uint32_t qf[4][4];
    #pragma unroll
    for (int s = 0; s < 4; s++)
        ldsm4(qf[s], smb + (qrowswz ^ (cbv | (s << 5))));

    float o[8][4];
    #pragma unroll
    for (int j = 0; j < 8; j++)
        o[j][0] = o[j][1] = o[j][2] = o[j][3] = 0.f;
    float rsl = 0.f, rsh = 0.f;

    // ======================= PHASE 1: rowsums + PV (no P stores) ============
    for (int t = 0; t <= qt; t++) {
        const int cur = t & 1, nxt = cur ^ 1;
        const bool hasNext = (t < qt);
        const uint32_t Kc = smb + KBUF(cur);
        const uint32_t Vc = smb + VBUF(cur);
        const int k0 = t * 128;
        const bool diag = (t == qt);
        const float* Kg = K + ((size_t)bh * SEQ + k0 + 128) * HD;
        const float* Vg = V + ((size_t)bh * SEQ + k0 + 128) * HD;

        #pragma unroll
        for (int h = 0; h < 4; h++) {
            float4 pk[2], pv[2];
            if (hasNext) {
                #pragma unroll
                for (int u = 0; u < 2; u++) {
                    int i = tid + (2 * h + u) * 256;
                    pk[u] = *(const float4*)(Kg + (i >> 4) * HD + (i & 15) * 4);
                    pv[u] = *(const float4*)(Vg + (i >> 4) * HD + (i & 15) * 4);
                }
            }

            if (!(diag && (2 * h > warp))) {
                float c[4][4];
                #pragma unroll
                for (int j = 0; j < 4; j++)
                    c[j][0] = c[j][1] = c[j][2] = c[j][3] = 0.f;

                #pragma unroll
                for (int s = 0; s < 4; s++) {
                    #pragma unroll
                    for (int pp = 0; pp < 2; pp++) {
                        uint32_t kh[4];
                        ldsm4(kh, Kc + ((ka0 + ((uint32_t)(2 * h + pp) << 11)) ^ (cbq | (s << 5))));
                        mma_f16(c[2 * pp],     qf[s], kh[0], kh[1]);
                        mma_f16(c[2 * pp + 1], qf[s], kh[2], kh[3]);
                    }
                }

                #pragma unroll
                for (int jl = 0; jl < 4; jl++) {
                    int kc = k0 + h * 32 + jl * 8 + 2 * (lane & 3);
                    c[jl][0] = (mql && (!diag || kc     + mn <= qrl)) ? __expf(c[jl][0]) : 0.f;
                    c[jl][1] = (mql && (!diag || kc + 1 + mn <= qrl)) ? __expf(c[jl][1]) : 0.f;
                    c[jl][2] = (mqh && (!diag || kc     + mn <= qrh)) ? __expf(c[jl][2]) : 0.f;
                    c[jl][3] = (mqh && (!diag || kc + 1 + mn <= qrh)) ? __expf(c[jl][3]) : 0.f;
                    rsl += c[jl][0] + c[jl][1];
                    rsh += c[jl][2] + c[jl][3];
                }

                #pragma unroll
                for (int sl = 0; sl < 2; sl++) {
                    uint32_t af[4];
                    af[0] = pack2h(c[2 * sl][0],     c[2 * sl][1]);
                    af[1] = pack2h(c[2 * sl][2],     c[2 * sl][3]);
                    af[2] = pack2h(c[2 * sl + 1][0], c[2 * sl + 1][1]);
                    af[3] = pack2h(c[2 * sl + 1][2], c[2 * sl + 1][3]);
                    uint32_t vrow = va0 + ((uint32_t)(2 * h + sl) << 11);
                    #pragma unroll
                    for (int p = 0; p < 4; p++) {
                        uint32_t bhr[4];
                        ldsm4t(bhr, Vc + (vrow ^ (cbv | (p << 5))));
                        mma_f16(o[2 * p],     af, bhr[0], bhr[1]);
                        mma_f16(o[2 * p + 1], af, bhr[2], bhr[3]);
                    }
                }
            }

            if (hasNext) {
                #pragma unroll
                for (int u = 0; u < 2; u++) {
                    int i = tid + (2 * h + u) * 256;
                    int row = i >> 4, c4 = i & 15;
                    uint32_t off = SWZ(row * 128 + c4 * 8);
                    *(uint2*)(sm + KBUF(nxt) + off) = make_uint2(
                        pack2h(pk[u].x, pk[u].y), pack2h(pk[u].z, pk[u].w));
                    *(uint2*)(sm + VBUF(nxt) + off) = make_uint2(
                        pack2h(pv[u].x, pv[u].y), pack2h(pv[u].z, pv[u].w));
                }
            }
        }
        __syncthreads();
    }

    // ---- rowsums -> inv; O store (scaled) ----
    rsl += __shfl_xor_sync(0xffffffffu, rsl, 1);
    rsl += __shfl_xor_sync(0xffffffffu, rsl, 2);
    rsh += __shfl_xor_sync(0xffffffffu, rsh, 1);
    rsh += __shfl_xor_sync(0xffffffffu, rsh, 2);
    const float il = (rsl > 0.f) ? (1.f / rsl) : 0.f;
    const float ih = (rsh > 0.f) ? (1.f / rsh) : 0.f;
    if ((lane & 3) == 0) { INV[rl] = il; INV[rh] = ih; }

    const int dcol = 2 * (lane & 3);
    #pragma unroll
    for (int j = 0; j < 8; j++) {
        *(float2*)(O + ((size_t)bh * SEQ + qrl) * HD + j * 8 + dcol) =
            make_float2(o[j][0] * il, o[j][1] * il);
        *(float2*)(O + ((size_t)bh * SEQ + qrh) * HD + j * 8 + dcol) =
            make_float2(o[j][2] * ih, o[j][3] * ih);
    }

    // ======================= PHASE 2: recompute + store normalized P ========
    // restage K tile 0 (L2-hot)
    __syncthreads();
    {
        const float* Kg = K + (size_t)bh * SEQ * HD;
        #pragma unroll
        for (int it = 0; it < 8; it++) {
            int i = tid + it * 256;
            int row = i >> 4, c4 = i & 15;
            uint32_t off = SWZ(row * 128 + c4 * 8);
            float4 v = *(const float4*)(Kg + row * HD + c4 * 4);
            *(uint2*)(sm + KBUF(0) + off) = make_uint2(
                pack2h(v.x, v.y), pack2h(v.z, v.w));
        }
    }
    __syncthreads();

    for (int t = 0; t <= qt; t++) {
        const int cur = t & 1, nxt = cur ^ 1;
        const bool hasNext = (t < qt);
        const uint32_t Kc = smb + KBUF(cur);
        const int k0 = t * 128;
        const bool diag = (t == qt);
        const float* Kg = K + ((size_t)bh * SEQ + k0 + 128) * HD;

        #pragma unroll
        for (int h = 0; h < 4; h++) {
            float4 pk[2];
            if (hasNext) {
                #pragma unroll
                for (int u = 0; u < 2; u++) {
                    int i = tid + (2 * h + u) * 256;
                    pk[u] = *(const float4*)(Kg + (i >> 4) * HD + (i & 15) * 4);
                }
            }

            if (diag && (2 * h > warp)) {
                // fully-masked chunk: write zeros
                #pragma unroll
                for (int jl = 0; jl < 4; jl++) {
                    int kc = k0 + h * 32 + jl * 8 + dcol;
                    *(float2*)(P + ((size_t)bh * SEQ + qrl) * SEQ + kc) = make_float2(0.f, 0.f);
                    *(float2*)(P + ((size_t)bh * SEQ + qrh) * SEQ + kc) = make_float2(0.f, 0.f);
                }
            } else {
                float c[4][4];
                #pragma unroll
                for (int j = 0; j < 4; j++)
                    c[j][0] = c[j][1] = c[j][2] = c[j][3] = 0.f;

                #pragma unroll
                for (int s = 0; s < 4; s++) {
                    #pragma unroll
                    for (int pp = 0; pp < 2; pp++) {
                        uint32_t kh[4];
                        ldsm4(kh, Kc + ((ka0 + ((uint32_t)(2 * h + pp) << 11)) ^ (cbq | (s << 5))));
                        mma_f16(c[2 * pp],     qf[s], kh[0], kh[1]);
                        mma_f16(c[2 * pp + 1], qf[s], kh[2], kh[3]);
                    }
                }

                #pragma unroll
                for (int jl = 0; jl < 4; jl++) {
                    int kc = k0 + h * 32 + jl * 8 + dcol;
                    float p0 = (mql && (!diag || kc     + mn <= qrl)) ? __expf(c[jl][0]) * il : 0.f;
                    float p1 = (mql && (!diag || kc + 1 + mn <= qrl)) ? __expf(c[jl][1]) * il : 0.f;
                    float p2 = (mqh && (!diag || kc     + mn <= qrh)) ? __expf(c[jl][2]) * ih : 0.f;
                    float p3 = (mqh && (!diag || kc + 1 + mn <= qrh)) ? __expf(c[jl][3]) * ih : 0.f;
                    *(float2*)(P + ((size_t)bh * SEQ + qrl) * SEQ + kc) = make_float2(p0, p1);
                    *(float2*)(P + ((size_t)bh * SEQ + qrh) * SEQ + kc) = make_float2(p2, p3);
                }
            }

            if (hasNext) {
                #pragma unroll
                for (int u = 0; u < 2; u++) {
                    int i = tid + (2 * h + u) * 256;
                    int row = i >> 4, c4 = i & 15;
                    uint32_t off = SWZ(row * 128 + c4 * 8);
                    *(uint2*)(sm + KBUF(nxt) + off) = make_uint2(
                        pack2h(pk[u].x, pk[u].y), pack2h(pk[u].z, pk[u].w));
                }
            }
        }
        __syncthreads();
    }
}

// ---------------------------------------------------------------------------
extern "C" void kernel_launch(void* const* d_in, const int* in_sizes, int n_in,
                              void* d_out, int out_size)
{
    const float* Q        = (const float*)d_in[0];
    const float* K        = (const float*)d_in[1];
    const float* V        = (const float*)d_in[2];
    const float* mask     = (const float*)d_in[3];
    const int*   mask_now = (const int*)d_in[4];

    float* O = (float*)d_out;                      // [B,H,S,D]
    float* P = O + (size_t)NBH * SEQ * HD;         // [B,H,S,S]

    cudaFuncSetAttribute(k_attn, cudaFuncAttributeMaxDynamicSharedMemorySize, 82432);

    k_attn<<<dim3(16, NBH), 256, 82432>>>(Q, K, V, mask, mask_now, P, O);
}

// round 11
// speedup vs baseline: 2.0322x; 1.0999x over previous
#include <cuda_runtime.h>
#include <cuda_fp16.h>
#include <cstdint>

#define SEQ 2048
#define HD  64
#define NBH 32

#define SWZ(x) ((x) ^ (((x) >> 3) & 0x70))

__device__ __forceinline__ uint32_t smem_u32(const void* p) {
    uint32_t a;
    asm("{ .reg .u64 t; cvta.to.shared.u64 t, %1; cvt.u32.u64 %0, t; }"
        : "=r"(a) : "l"(p));
    return a;
}
__device__ __forceinline__ void ldsm4(uint32_t* d, uint32_t a) {
    asm volatile("ldmatrix.sync.aligned.m8n8.x4.shared.b16 {%0,%1,%2,%3}, [%4];"
        : "=r"(d[0]), "=r"(d[1]), "=r"(d[2]), "=r"(d[3]) : "r"(a));
}
__device__ __forceinline__ void ldsm4t(uint32_t* d, uint32_t a) {
    asm volatile("ldmatrix.sync.aligned.m8n8.x4.trans.shared.b16 {%0,%1,%2,%3}, [%4];"
        : "=r"(d[0]), "=r"(d[1]), "=r"(d[2]), "=r"(d[3]) : "r"(a));
}
__device__ __forceinline__ void mma_f16(float* c, const uint32_t* a,
                                        uint32_t b0, uint32_t b1) {
    asm volatile(
        "mma.sync.aligned.m16n8k16.row.col.f32.f16.f16.f32 "
        "{%0,%1,%2,%3}, {%4,%5,%6,%7}, {%8,%9}, {%0,%1,%2,%3};"
        : "+f"(c[0]), "+f"(c[1]), "+f"(c[2]), "+f"(c[3])
        : "r"(a[0]), "r"(a[1]), "r"(a[2]), "r"(a[3]), "r"(b0), "r"(b1));
}
__device__ __forceinline__ uint32_t pack2h(float x0, float x1) {
    __half2 h = __floats2half2_rn(x0, x1);
    return *reinterpret_cast<uint32_t*>(&h);
}
__device__ __forceinline__ uint32_t swzrow(int r) {
    uint32_t x = (uint32_t)r << 7;
    return x ^ ((x >> 3) & 0x70);
}

// smem map: QF 0..16K (persistent), K dbuf 16K..48K, V dbuf 48K..80K, INV @80K
#define KBUF(b) (16384u + (b) * 16384u)
#define VBUF(b) (49152u + (b) * 16384u)

// Q pre-scale: (1/8) * log2(e), so scores are in log2 domain -> exp2f
#define QSCALE 0.1803368801111204f

__global__ __launch_bounds__(256, 2) void k_attn(
    const float* __restrict__ Q, const float* __restrict__ K,
    const float* __restrict__ V, const float* __restrict__ mask,
    const int* __restrict__ mask_now,
    float* __restrict__ P, float* __restrict__ O)
{
    extern __shared__ char sm[];
    const uint32_t smb = smem_u32(sm);
    const int tid = threadIdx.x, lane = tid & 31, warp = tid >> 5;
    const int g = lane >> 3, r8 = lane & 7;
    const int qt = 15 - blockIdx.x, bh = blockIdx.y, b = bh >> 4;
    const int q0 = qt * 128;
    const int mn = mask_now[0];

    float* INV = (float*)(sm + 81920);

    // ---- stage Q (pre-scaled) + tile-0 K/V fp16 planes ----
    {
        const float* Qg = Q + ((size_t)bh * SEQ + q0) * HD;
        const float* Kg = K + (size_t)bh * SEQ * HD;
        const float* Vg = V + (size_t)bh * SEQ * HD;
        #pragma unroll
        for (int it = 0; it < 8; it++) {
            int i = tid + it * 256;
            int row = i >> 4, c4 = i & 15;
            uint32_t off = SWZ(row * 128 + c4 * 8);
            float4 v = *(const float4*)(Qg + row * HD + c4 * 4);
            *(uint2*)(sm + 0 + off) = make_uint2(
                pack2h(v.x * QSCALE, v.y * QSCALE),
                pack2h(v.z * QSCALE, v.w * QSCALE));
            v = *(const float4*)(Kg + row * HD + c4 * 4);
            *(uint2*)(sm + KBUF(0) + off) = make_uint2(
                pack2h(v.x, v.y), pack2h(v.z, v.w));
            v = *(const float4*)(Vg + row * HD + c4 * 4);
            *(uint2*)(sm + VBUF(0) + off) = make_uint2(
                pack2h(v.x, v.y), pack2h(v.z, v.w));
        }
    }

    // zero-fill P cols [q0+128, SEQ)
    {
        const int c0 = q0 + 128;
        const int w = (SEQ - c0) >> 2;
        for (int r = warp; r < 128; r += 8) {
            float4* rowp = (float4*)(P + ((size_t)bh * SEQ + q0 + r) * SEQ + c0);
            for (int cc = lane; cc < w; cc += 32)
                rowp[cc] = make_float4(0.f, 0.f, 0.f, 0.f);
        }
    }

    const int rl = warp * 16 + (lane >> 2), rh = rl + 8;
    const int qrl = q0 + rl, qrh = q0 + rh;
    const bool mql = mask[(size_t)b * SEQ + qrl] != 0.f;
    const bool mqh = mask[(size_t)b * SEQ + qrh] != 0.f;

    const uint32_t cbq = (uint32_t)(lane & 8) << 1;
    const uint32_t cbv = (uint32_t)(g >> 1) << 4;
    const uint32_t ka0 = swzrow(((g >> 1) << 3) + r8);
    const uint32_t va0 = swzrow(((g & 1) << 3) + r8);
    const uint32_t qrowswz = swzrow(warp * 16 + ((g & 1) << 3) + r8);

    __syncthreads();

    uint32_t qf[4][4];
    #pragma unroll
    for (int s = 0; s < 4; s++)
        ldsm4(qf[s], smb + (qrowswz ^ (cbv | (s << 5))));

    float o[8][4];
    #pragma unroll
    for (int j = 0; j < 8; j++)
        o[j][0] = o[j][1] = o[j][2] = o[j][3] = 0.f;
    float rsl = 0.f, rsh = 0.f;

    // ======================= PHASE 1: rowsums + PV (no P stores) ============
    for (int t = 0; t <= qt; t++) {
        const int cur = t & 1, nxt = cur ^ 1;
        const bool hasNext = (t < qt);
        const uint32_t Kc = smb + KBUF(cur);
        const uint32_t Vc = smb + VBUF(cur);
        const int k0 = t * 128;
        const bool diag = (t == qt);
        const float* Kg = K + ((size_t)bh * SEQ + k0 + 128) * HD;
        const float* Vg = V + ((size_t)bh * SEQ + k0 + 128) * HD;

        #pragma unroll
        for (int h = 0; h < 4; h++) {
            float4 pk[2], pv[2];
            if (hasNext) {
                #pragma unroll
                for (int u = 0; u < 2; u++) {
                    int i = tid + (2 * h + u) * 256;
                    pk[u] = *(const float4*)(Kg + (i >> 4) * HD + (i & 15) * 4);
                    pv[u] = *(const float4*)(Vg + (i >> 4) * HD + (i & 15) * 4);
                }
            }

            if (!(diag && (2 * h > warp))) {
                float c[4][4];
                #pragma unroll
                for (int j = 0; j < 4; j++)
                    c[j][0] = c[j][1] = c[j][2] = c[j][3] = 0.f;

                #pragma unroll
                for (int s = 0; s < 4; s++) {
                    #pragma unroll
                    for (int pp = 0; pp < 2; pp++) {
                        uint32_t kh[4];
                        ldsm4(kh, Kc + ((ka0 + ((uint32_t)(2 * h + pp) << 11)) ^ (cbq | (s << 5))));
                        mma_f16(c[2 * pp],     qf[s], kh[0], kh[1]);
                        mma_f16(c[2 * pp + 1], qf[s], kh[2], kh[3]);
                    }
                }

                #pragma unroll
                for (int jl = 0; jl < 4; jl++) {
                    int kc = k0 + h * 32 + jl * 8 + 2 * (lane & 3);
                    c[jl][0] = (mql && (!diag || kc     + mn <= qrl)) ? exp2f(c[jl][0]) : 0.f;
                    c[jl][1] = (mql && (!diag || kc + 1 + mn <= qrl)) ? exp2f(c[jl][1]) : 0.f;
                    c[jl][2] = (mqh && (!diag || kc     + mn <= qrh)) ? exp2f(c[jl][2]) : 0.f;
                    c[jl][3] = (mqh && (!diag || kc + 1 + mn <= qrh)) ? exp2f(c[jl][3]) : 0.f;
                    rsl += c[jl][0] + c[jl][1];
                    rsh += c[jl][2] + c[jl][3];
                }

                #pragma unroll
                for (int sl = 0; sl < 2; sl++) {
                    uint32_t af[4];
                    af[0] = pack2h(c[2 * sl][0],     c[2 * sl][1]);
                    af[1] = pack2h(c[2 * sl][2],     c[2 * sl][3]);
                    af[2] = pack2h(c[2 * sl + 1][0], c[2 * sl + 1][1]);
                    af[3] = pack2h(c[2 * sl + 1][2], c[2 * sl + 1][3]);
                    uint32_t vrow = va0 + ((uint32_t)(2 * h + sl) << 11);
                    #pragma unroll
                    for (int p = 0; p < 4; p++) {
                        uint32_t bhr[4];
                        ldsm4t(bhr, Vc + (vrow ^ (cbv | (p << 5))));
                        mma_f16(o[2 * p],     af, bhr[0], bhr[1]);
                        mma_f16(o[2 * p + 1], af, bhr[2], bhr[3]);
                    }
                }
            }

            if (hasNext) {
                #pragma unroll
                for (int u = 0; u < 2; u++) {
                    int i = tid + (2 * h + u) * 256;
                    int row = i >> 4, c4 = i & 15;
                    uint32_t off = SWZ(row * 128 + c4 * 8);
                    *(uint2*)(sm + KBUF(nxt) + off) = make_uint2(
                        pack2h(pk[u].x, pk[u].y), pack2h(pk[u].z, pk[u].w));
                    *(uint2*)(sm + VBUF(nxt) + off) = make_uint2(
                        pack2h(pv[u].x, pv[u].y), pack2h(pv[u].z, pv[u].w));
                }
            }
        }
        __syncthreads();
    }

    // ---- rowsums -> inv; O store (scaled) ----
    rsl += __shfl_xor_sync(0xffffffffu, rsl, 1);
    rsl += __shfl_xor_sync(0xffffffffu, rsl, 2);
    rsh += __shfl_xor_sync(0xffffffffu, rsh, 1);
    rsh += __shfl_xor_sync(0xffffffffu, rsh, 2);
    const float il = (rsl > 0.f) ? (1.f / rsl) : 0.f;
    const float ih = (rsh > 0.f) ? (1.f / rsh) : 0.f;
    if ((lane & 3) == 0) { INV[rl] = il; INV[rh] = ih; }

    const int dcol = 2 * (lane & 3);
    #pragma unroll
    for (int j = 0; j < 8; j++) {
        *(float2*)(O + ((size_t)bh * SEQ + qrl) * HD + j * 8 + dcol) =
            make_float2(o[j][0] * il, o[j][1] * il);
        *(float2*)(O + ((size_t)bh * SEQ + qrh) * HD + j * 8 + dcol) =
            make_float2(o[j][2] * ih, o[j][3] * ih);
    }

    // ======================= PHASE 2: recompute + store normalized P ========
    // Run BACKWARDS: K tile qt is still resident in buffer (qt&1) from phase 1.
    // Strength-reduced store pointers: float2 units, (lane&3) folded in.
    float2* const Prl = (float2*)(P + ((size_t)bh * SEQ + qrl) * SEQ) + (lane & 3);
    float2* const Prh = (float2*)(P + ((size_t)bh * SEQ + qrh) * SEQ) + (lane & 3);

    for (int t = qt; t >= 0; t--) {
        const int cur = t & 1, nxt = cur ^ 1;
        const bool hasNext = (t > 0);
        const uint32_t Kc = smb + KBUF(cur);
        const int k0 = t * 128;
        const bool diag = (t == qt);
        const float* Kg = K + ((size_t)bh * SEQ + k0 - 128) * HD;   // tile t-1
        float2* const prl = Prl + (k0 >> 1);
        float2* const prh = Prh + (k0 >> 1);

        #pragma unroll
        for (int h = 0; h < 4; h++) {
            float4 pk[2];
            if (hasNext) {
                #pragma unroll
                for (int u = 0; u < 2; u++) {
                    int i = tid + (2 * h + u) * 256;
                    pk[u] = *(const float4*)(Kg + (i >> 4) * HD + (i & 15) * 4);
                }
            }

            if (diag && (2 * h > warp)) {
                #pragma unroll
                for (int jl = 0; jl < 4; jl++) {
                    prl[h * 16 + jl * 4] = make_float2(0.f, 0.f);
                    prh[h * 16 + jl * 4] = make_float2(0.f, 0.f);
                }
            } else {
                float c[4][4];
                #pragma unroll
                for (int j = 0; j < 4; j++)
                    c[j][0] = c[j][1] = c[j][2] = c[j][3] = 0.f;

                #pragma unroll
                for (int s = 0; s < 4; s++) {
                    #pragma unroll
                    for (int pp = 0; pp < 2; pp++) {
                        uint32_t kh[4];
                        ldsm4(kh, Kc + ((ka0 + ((uint32_t)(2 * h + pp) << 11)) ^ (cbq | (s << 5))));
                        mma_f16(c[2 * pp],     qf[s], kh[0], kh[1]);
                        mma_f16(c[2 * pp + 1], qf[s], kh[2], kh[3]);
                    }
                }

                #pragma unroll
                for (int jl = 0; jl < 4; jl++) {
                    int kc = k0 + h * 32 + jl * 8 + dcol;
                    float p0 = (mql && (!diag || kc     + mn <= qrl)) ? exp2f(c[jl][0]) * il : 0.f;
                    float p1 = (mql && (!diag || kc + 1 + mn <= qrl)) ? exp2f(c[jl][1]) * il : 0.f;
                    float p2 = (mqh && (!diag || kc     + mn <= qrh)) ? exp2f(c[jl][2]) * ih : 0.f;
                    float p3 = (mqh && (!diag || kc + 1 + mn <= qrh)) ? exp2f(c[jl][3]) * ih : 0.f;
                    prl[h * 16 + jl * 4] = make_float2(p0, p1);
                    prh[h * 16 + jl * 4] = make_float2(p2, p3);
                }
            }

            if (hasNext) {
                #pragma unroll
                for (int u = 0; u < 2; u++) {
                    int i = tid + (2 * h + u) * 256;
                    int row = i >> 4, c4 = i & 15;
                    uint32_t off = SWZ(row * 128 + c4 * 8);
                    *(uint2*)(sm + KBUF(nxt) + off) = make_uint2(
                        pack2h(pk[u].x, pk[u].y), pack2h(pk[u].z, pk[u].w));
                }
            }
        }
        __syncthreads();
    }
}

// ---------------------------------------------------------------------------
extern "C" void kernel_launch(void* const* d_in, const int* in_sizes, int n_in,
                              void* d_out, int out_size)
{
    const float* Q        = (const float*)d_in[0];
    const float* K        = (const float*)d_in[1];
    const float* V        = (const float*)d_in[2];
    const float* mask     = (const float*)d_in[3];
    const int*   mask_now = (const int*)d_in[4];

    float* O = (float*)d_out;                      // [B,H,S,D]
    float* P = O + (size_t)NBH * SEQ * HD;         // [B,H,S,S]

    cudaFuncSetAttribute(k_attn, cudaFuncAttributeMaxDynamicSharedMemorySize, 82432);

    k_attn<<<dim3(16, NBH), 256, 82432>>>(Q, K, V, mask, mask_now, P, O);
}

// round 12
// speedup vs baseline: 2.1246x; 1.0454x over previous
#include <cuda_runtime.h>
#include <cuda_fp16.h>
#include <cstdint>

#define SEQ 2048
#define HD  64
#define NBH 32

#define SWZ(x) ((x) ^ (((x) >> 3) & 0x70))

__device__ __forceinline__ uint32_t smem_u32(const void* p) {
    uint32_t a;
    asm("{ .reg .u64 t; cvta.to.shared.u64 t, %1; cvt.u32.u64 %0, t; }"
        : "=r"(a) : "l"(p));
    return a;
}
__device__ __forceinline__ void ldsm4(uint32_t* d, uint32_t a) {
    asm volatile("ldmatrix.sync.aligned.m8n8.x4.shared.b16 {%0,%1,%2,%3}, [%4];"
        : "=r"(d[0]), "=r"(d[1]), "=r"(d[2]), "=r"(d[3]) : "r"(a));
}
__device__ __forceinline__ void ldsm4t(uint32_t* d, uint32_t a) {
    asm volatile("ldmatrix.sync.aligned.m8n8.x4.trans.shared.b16 {%0,%1,%2,%3}, [%4];"
        : "=r"(d[0]), "=r"(d[1]), "=r"(d[2]), "=r"(d[3]) : "r"(a));
}
__device__ __forceinline__ void mma_f16(float* c, const uint32_t* a,
                                        uint32_t b0, uint32_t b1) {
    asm volatile(
        "mma.sync.aligned.m16n8k16.row.col.f32.f16.f16.f32 "
        "{%0,%1,%2,%3}, {%4,%5,%6,%7}, {%8,%9}, {%0,%1,%2,%3};"
        : "+f"(c[0]), "+f"(c[1]), "+f"(c[2]), "+f"(c[3])
        : "r"(a[0]), "r"(a[1]), "r"(a[2]), "r"(a[3]), "r"(b0), "r"(b1));
}
__device__ __forceinline__ uint32_t pack2h(float x0, float x1) {
    __half2 h = __floats2half2_rn(x0, x1);
    return *reinterpret_cast<uint32_t*>(&h);
}
__device__ __forceinline__ uint32_t swzrow(int r) {
    uint32_t x = (uint32_t)r << 7;
    return x ^ ((x >> 3) & 0x70);
}

// smem map: QF 0..16K (persistent), K dbuf 16K..48K, V dbuf 48K..80K, INV @80K
#define KBUF(b) (16384u + (b) * 16384u)
#define VBUF(b) (49152u + (b) * 16384u)

// Q pre-scale: (1/8) * log2(e) -> scores in log2 domain -> exp2f
#define QSCALE 0.1803368801111204f

__global__ __launch_bounds__(256, 2) void k_attn(
    const float* __restrict__ Q, const float* __restrict__ K,
    const float* __restrict__ V, const float* __restrict__ mask,
    const int* __restrict__ mask_now,
    float* __restrict__ P, float* __restrict__ O)
{
    extern __shared__ char sm[];
    const uint32_t smb = smem_u32(sm);
    const int tid = threadIdx.x, lane = tid & 31, warp = tid >> 5;
    const int g = lane >> 3, r8 = lane & 7;
    const int qt = 15 - blockIdx.x, bh = blockIdx.y, b = bh >> 4;
    const int q0 = qt * 128;
    const int mn = mask_now[0];

    float* INV = (float*)(sm + 81920);

    // per-thread staging bases (slice s in [0,8): gmem +s*1024 elems, smem +s*2048)
    const int base_elem = (tid >> 4) * HD + (tid & 15) * 4;
    const uint32_t cvt0 = SWZ((uint32_t)((tid >> 4) * 128 + (tid & 15) * 8));

    // ---- stage Q (pre-scaled) + tile-0 K/V fp16 planes ----
    {
        const float* Qg = Q + ((size_t)bh * SEQ + q0) * HD + base_elem;
        const float* Kg = K + (size_t)bh * SEQ * HD + base_elem;
        const float* Vg = V + (size_t)bh * SEQ * HD + base_elem;
        #pragma unroll
        for (int s = 0; s < 8; s++) {
            uint32_t off = cvt0 + s * 2048;
            float4 v = *(const float4*)(Qg + s * 1024);
            *(uint2*)(sm + 0 + off) = make_uint2(
                pack2h(v.x * QSCALE, v.y * QSCALE),
                pack2h(v.z * QSCALE, v.w * QSCALE));
            v = *(const float4*)(Kg + s * 1024);
            *(uint2*)(sm + KBUF(0) + off) = make_uint2(
                pack2h(v.x, v.y), pack2h(v.z, v.w));
            v = *(const float4*)(Vg + s * 1024);
            *(uint2*)(sm + VBUF(0) + off) = make_uint2(
                pack2h(v.x, v.y), pack2h(v.z, v.w));
        }
    }

    // zero-fill P cols [q0+128, SEQ)
    {
        const int c0 = q0 + 128;
        const int w = (SEQ - c0) >> 2;
        for (int r = warp; r < 128; r += 8) {
            float4* rowp = (float4*)(P + ((size_t)bh * SEQ + q0 + r) * SEQ + c0);
            for (int cc = lane; cc < w; cc += 32)
                rowp[cc] = make_float4(0.f, 0.f, 0.f, 0.f);
        }
    }

    const int rl = warp * 16 + (lane >> 2), rh = rl + 8;
    const int qrl = q0 + rl, qrh = q0 + rh;
    const bool mql = mask[(size_t)b * SEQ + qrl] != 0.f;
    const bool mqh = mask[(size_t)b * SEQ + qrh] != 0.f;
    const int dcol = 2 * (lane & 3);
    // causal thresholds: element col kc kept iff kc <= q - mn
    const int tcl = qrl - mn - dcol;     // cond for +0 elem: base <= tcl ; +1: base <= tcl-1
    const int tch = qrh - mn - dcol;

    const uint32_t cbq = (uint32_t)(lane & 8) << 1;
    const uint32_t cbv = (uint32_t)(g >> 1) << 4;
    const uint32_t ka0 = swzrow(((g >> 1) << 3) + r8);
    const uint32_t va0 = swzrow(((g & 1) << 3) + r8);
    const uint32_t qrowswz = swzrow(warp * 16 + ((g & 1) << 3) + r8);

    __syncthreads();

    uint32_t qf[4][4];
    #pragma unroll
    for (int s = 0; s < 4; s++)
        ldsm4(qf[s], smb + (qrowswz ^ (cbv | (s << 5))));

    float o[8][4];
    #pragma unroll
    for (int j = 0; j < 8; j++)
        o[j][0] = o[j][1] = o[j][2] = o[j][3] = 0.f;
    float rsl = 0.f, rsh = 0.f;

    // ======================= PHASE 1: rowsums + PV (no P stores) ============
    for (int t = 0; t <= qt; t++) {
        const int cur = t & 1, nxt = cur ^ 1;
        const bool hasNext = (t < qt);
        const uint32_t Kc = smb + KBUF(cur);
        const uint32_t Vc = smb + VBUF(cur);
        const int k0 = t * 128;
        const bool diag = (t == qt);
        const float* Kg = K + ((size_t)bh * SEQ + k0 + 128) * HD + base_elem;
        const float* Vg = V + ((size_t)bh * SEQ + k0 + 128) * HD + base_elem;

        #pragma unroll
        for (int h = 0; h < 4; h++) {
            float4 pk[2], pv[2];
            if (hasNext) {
                #pragma unroll
                for (int u = 0; u < 2; u++) {
                    pk[u] = *(const float4*)(Kg + (2 * h + u) * 1024);
                    pv[u] = *(const float4*)(Vg + (2 * h + u) * 1024);
                }
            }

            if (!(diag && (2 * h > warp))) {
                float c[4][4];
                #pragma unroll
                for (int j = 0; j < 4; j++)
                    c[j][0] = c[j][1] = c[j][2] = c[j][3] = 0.f;

                #pragma unroll
                for (int s = 0; s < 4; s++) {
                    #pragma unroll
                    for (int pp = 0; pp < 2; pp++) {
                        uint32_t kh[4];
                        ldsm4(kh, Kc + ((ka0 + ((uint32_t)(2 * h + pp) << 11)) ^ (cbq | (s << 5))));
                        mma_f16(c[2 * pp],     qf[s], kh[0], kh[1]);
                        mma_f16(c[2 * pp + 1], qf[s], kh[2], kh[3]);
                    }
                }

                if (!diag) {
                    // no causal predicates needed off-diagonal
                    #pragma unroll
                    for (int jl = 0; jl < 4; jl++) {
                        c[jl][0] = mql ? exp2f(c[jl][0]) : 0.f;
                        c[jl][1] = mql ? exp2f(c[jl][1]) : 0.f;
                        c[jl][2] = mqh ? exp2f(c[jl][2]) : 0.f;
                        c[jl][3] = mqh ? exp2f(c[jl][3]) : 0.f;
                        rsl += c[jl][0] + c[jl][1];
                        rsh += c[jl][2] + c[jl][3];
                    }
                } else {
                    #pragma unroll
                    for (int jl = 0; jl < 4; jl++) {
                        int bs = k0 + h * 32 + jl * 8;
                        c[jl][0] = (mql && bs <= tcl    ) ? exp2f(c[jl][0]) : 0.f;
                        c[jl][1] = (mql && bs <= tcl - 1) ? exp2f(c[jl][1]) : 0.f;
                        c[jl][2] = (mqh && bs <= tch    ) ? exp2f(c[jl][2]) : 0.f;
                        c[jl][3] = (mqh && bs <= tch - 1) ? exp2f(c[jl][3]) : 0.f;
                        rsl += c[jl][0] + c[jl][1];
                        rsh += c[jl][2] + c[jl][3];
                    }
                }

                #pragma unroll
                for (int sl = 0; sl < 2; sl++) {
                    uint32_t af[4];
                    af[0] = pack2h(c[2 * sl][0],     c[2 * sl][1]);
                    af[1] = pack2h(c[2 * sl][2],     c[2 * sl][3]);
                    af[2] = pack2h(c[2 * sl + 1][0], c[2 * sl + 1][1]);
                    af[3] = pack2h(c[2 * sl + 1][2], c[2 * sl + 1][3]);
                    uint32_t vrow = va0 + ((uint32_t)(2 * h + sl) << 11);
                    #pragma unroll
                    for (int p = 0; p < 4; p++) {
                        uint32_t bhr[4];
                        ldsm4t(bhr, Vc + (vrow ^ (cbv | (p << 5))));
                        mma_f16(o[2 * p],     af, bhr[0], bhr[1]);
                        mma_f16(o[2 * p + 1], af, bhr[2], bhr[3]);
                    }
                }
            }

            if (hasNext) {
                #pragma unroll
                for (int u = 0; u < 2; u++) {
                    uint32_t off = cvt0 + (2 * h + u) * 2048;
                    *(uint2*)(sm + KBUF(nxt) + off) = make_uint2(
                        pack2h(pk[u].x, pk[u].y), pack2h(pk[u].z, pk[u].w));
                    *(uint2*)(sm + VBUF(nxt) + off) = make_uint2(
                        pack2h(pv[u].x, pv[u].y), pack2h(pv[u].z, pv[u].w));
                }
            }
        }
        __syncthreads();
    }

    // ---- rowsums -> inv; O store (scaled) ----
    rsl += __shfl_xor_sync(0xffffffffu, rsl, 1);
    rsl += __shfl_xor_sync(0xffffffffu, rsl, 2);
    rsh += __shfl_xor_sync(0xffffffffu, rsh, 1);
    rsh += __shfl_xor_sync(0xffffffffu, rsh, 2);
    const float il = (rsl > 0.f) ? (1.f / rsl) : 0.f;
    const float ih = (rsh > 0.f) ? (1.f / rsh) : 0.f;
    if ((lane & 3) == 0) { INV[rl] = il; INV[rh] = ih; }

    #pragma unroll
    for (int j = 0; j < 8; j++) {
        *(float2*)(O + ((size_t)bh * SEQ + qrl) * HD + j * 8 + dcol) =
            make_float2(o[j][0] * il, o[j][1] * il);
        *(float2*)(O + ((size_t)bh * SEQ + qrh) * HD + j * 8 + dcol) =
            make_float2(o[j][2] * ih, o[j][3] * ih);
    }

    // ======================= PHASE 2: recompute + store normalized P ========
    // Run BACKWARDS: K tile qt is still resident in buffer (qt&1) from phase 1.
    float2* const Prl = (float2*)(P + ((size_t)bh * SEQ + qrl) * SEQ) + (lane & 3);
    float2* const Prh = (float2*)(P + ((size_t)bh * SEQ + qrh) * SEQ) + (lane & 3);

    for (int t = qt; t >= 0; t--) {
        const int cur = t & 1, nxt = cur ^ 1;
        const bool hasNext = (t > 0);
        const uint32_t Kc = smb + KBUF(cur);
        const int k0 = t * 128;
        const bool diag = (t == qt);
        const float* Kg = K + ((size_t)bh * SEQ + k0 - 128) * HD + base_elem;  // tile t-1
        float2* const prl = Prl + (k0 >> 1);
        float2* const prh = Prh + (k0 >> 1);

        #pragma unroll
        for (int h = 0; h < 4; h++) {
            float4 pk[2];
            if (hasNext) {
                #pragma unroll
                for (int u = 0; u < 2; u++)
                    pk[u] = *(const float4*)(Kg + (2 * h + u) * 1024);
            }

            if (diag && (2 * h > warp)) {
                #pragma unroll
                for (int jl = 0; jl < 4; jl++) {
                    prl[h * 16 + jl * 4] = make_float2(0.f, 0.f);
                    prh[h * 16 + jl * 4] = make_float2(0.f, 0.f);
                }
            } else {
                float c[4][4];
                #pragma unroll
                for (int j = 0; j < 4; j++)
                    c[j][0] = c[j][1] = c[j][2] = c[j][3] = 0.f;

                #pragma unroll
                for (int s = 0; s < 4; s++) {
                    #pragma unroll
                    for (int pp = 0; pp < 2; pp++) {
                        uint32_t kh[4];
                        ldsm4(kh, Kc + ((ka0 + ((uint32_t)(2 * h + pp) << 11)) ^ (cbq | (s << 5))));
                        mma_f16(c[2 * pp],     qf[s], kh[0], kh[1]);
                        mma_f16(c[2 * pp + 1], qf[s], kh[2], kh[3]);
                    }
                }

                if (!diag) {
                    #pragma unroll
                    for (int jl = 0; jl < 4; jl++) {
                        float p0 = mql ? exp2f(c[jl][0]) * il : 0.f;
                        float p1 = mql ? exp2f(c[jl][1]) * il : 0.f;
                        float p2 = mqh ? exp2f(c[jl][2]) * ih : 0.f;
                        float p3 = mqh ? exp2f(c[jl][3]) * ih : 0.f;
                        prl[h * 16 + jl * 4] = make_float2(p0, p1);
                        prh[h * 16 + jl * 4] = make_float2(p2, p3);
                    }
                } else {
                    #pragma unroll
                    for (int jl = 0; jl < 4; jl++) {
                        int bs = k0 + h * 32 + jl * 8;
                        float p0 = (mql && bs <= tcl    ) ? exp2f(c[jl][0]) * il : 0.f;
                        float p1 = (mql && bs <= tcl - 1) ? exp2f(c[jl][1]) * il : 0.f;
                        float p2 = (mqh && bs <= tch    ) ? exp2f(c[jl][2]) * ih : 0.f;
                        float p3 = (mqh && bs <= tch - 1) ? exp2f(c[jl][3]) * ih : 0.f;
                        prl[h * 16 + jl * 4] = make_float2(p0, p1);
                        prh[h * 16 + jl * 4] = make_float2(p2, p3);
                    }
                }
            }

            if (hasNext) {
                #pragma unroll
                for (int u = 0; u < 2; u++) {
                    uint32_t off = cvt0 + (2 * h + u) * 2048;
                    *(uint2*)(sm + KBUF(nxt) + off) = make_uint2(
                        pack2h(pk[u].x, pk[u].y), pack2h(pk[u].z, pk[u].w));
                }
            }
        }
        __syncthreads();
    }
}

// ---------------------------------------------------------------------------
extern "C" void kernel_launch(void* const* d_in, const int* in_sizes, int n_in,
                              void* d_out, int out_size)
{
    const float* Q        = (const float*)d_in[0];
    const float* K        = (const float*)d_in[1];
    const float* V        = (const float*)d_in[2];
    const float* mask     = (const float*)d_in[3];
    const int*   mask_now = (const int*)d_in[4];

    float* O = (float*)d_out;                      // [B,H,S,D]
    float* P = O + (size_t)NBH * SEQ * HD;         // [B,H,S,S]

    cudaFuncSetAttribute(k_attn, cudaFuncAttributeMaxDynamicSharedMemorySize, 82432);

    k_attn<<<dim3(16, NBH), 256, 82432>>>(Q, K, V, mask, mask_now, P, O);
}

// round 14
// speedup vs baseline: 2.1644x; 1.0188x over previous
#include <cuda_runtime.h>
#include <cuda_fp16.h>
#include <cstdint>

#define SEQ 2048
#define HD  64
#define NBH 32

#define SWZ(x) ((x) ^ (((x) >> 3) & 0x70))

__device__ __forceinline__ uint32_t smem_u32(const void* p) {
    uint32_t a;
    asm("{ .reg .u64 t; cvta.to.shared.u64 t, %1; cvt.u32.u64 %0, t; }"
        : "=r"(a) : "l"(p));
    return a;
}
__device__ __forceinline__ void ldsm4(uint32_t* d, uint32_t a) {
    asm volatile("ldmatrix.sync.aligned.m8n8.x4.shared.b16 {%0,%1,%2,%3}, [%4];"
        : "=r"(d[0]), "=r"(d[1]), "=r"(d[2]), "=r"(d[3]) : "r"(a));
}
__device__ __forceinline__ void ldsm4t(uint32_t* d, uint32_t a) {
    asm volatile("ldmatrix.sync.aligned.m8n8.x4.trans.shared.b16 {%0,%1,%2,%3}, [%4];"
        : "=r"(d[0]), "=r"(d[1]), "=r"(d[2]), "=r"(d[3]) : "r"(a));
}
__device__ __forceinline__ void mma_f16(float* c, const uint32_t* a,
                                        uint32_t b0, uint32_t b1) {
    asm volatile(
        "mma.sync.aligned.m16n8k16.row.col.f32.f16.f16.f32 "
        "{%0,%1,%2,%3}, {%4,%5,%6,%7}, {%8,%9}, {%0,%1,%2,%3};"
        : "+f"(c[0]), "+f"(c[1]), "+f"(c[2]), "+f"(c[3])
        : "r"(a[0]), "r"(a[1]), "r"(a[2]), "r"(a[3]), "r"(b0), "r"(b1));
}
__device__ __forceinline__ uint32_t pack2h(float x0, float x1) {
    __half2 h = __floats2half2_rn(x0, x1);
    return *reinterpret_cast<uint32_t*>(&h);
}
__device__ __forceinline__ uint32_t swzrow(int r) {
    uint32_t x = (uint32_t)r << 7;
    return x ^ ((x >> 3) & 0x70);
}

// smem map: QF 0..16K (persistent), K dbuf 16K..48K, V dbuf 48K..80K
// phase 2 reuses the V area (free) as warp-private store-bounce slabs.
#define KBUF(b) (16384u + (b) * 16384u)
#define VBUF(b) (49152u + (b) * 16384u)

// Q pre-scale: (1/8) * log2(e) -> scores in log2 domain -> exp2f
#define QSCALE 0.1803368801111204f

__global__ __launch_bounds__(256, 2) void k_attn(
    const float* __restrict__ Q, const float* __restrict__ K,
    const float* __restrict__ V, const float* __restrict__ mask,
    const int* __restrict__ mask_now,
    float* __restrict__ P, float* __restrict__ O)
{
    extern __shared__ char sm[];
    const uint32_t smb = smem_u32(sm);
    const int tid = threadIdx.x, lane = tid & 31, warp = tid >> 5;
    const int g = lane >> 3, r8 = lane & 7;
    const int qt = 15 - blockIdx.x, bh = blockIdx.y, b = bh >> 4;
    const int q0 = qt * 128;
    const int mn = mask_now[0];

    // per-thread staging bases (slice s in [0,8): gmem +s*1024 elems, smem +s*2048)
    const int base_elem = (tid >> 4) * HD + (tid & 15) * 4;
    const uint32_t cvt0 = SWZ((uint32_t)((tid >> 4) * 128 + (tid & 15) * 8));

    // ---- stage Q (pre-scaled) + tile-0 K/V fp16 planes ----
    {
        const float* Qg = Q + ((size_t)bh * SEQ + q0) * HD + base_elem;
        const float* Kg = K + (size_t)bh * SEQ * HD + base_elem;
        const float* Vg = V + (size_t)bh * SEQ * HD + base_elem;
        #pragma unroll
        for (int s = 0; s < 8; s++) {
            uint32_t off = cvt0 + s * 2048;
            float4 v = *(const float4*)(Qg + s * 1024);
            *(uint2*)(sm + 0 + off) = make_uint2(
                pack2h(v.x * QSCALE, v.y * QSCALE),
                pack2h(v.z * QSCALE, v.w * QSCALE));
            v = *(const float4*)(Kg + s * 1024);
            *(uint2*)(sm + KBUF(0) + off) = make_uint2(
                pack2h(v.x, v.y), pack2h(v.z, v.w));
            v = *(const float4*)(Vg + s * 1024);
            *(uint2*)(sm + VBUF(0) + off) = make_uint2(
                pack2h(v.x, v.y), pack2h(v.z, v.w));
        }
    }

    // zero-fill P cols [q0+128, SEQ) -- streaming stores
    {
        const int c0 = q0 + 128;
        const int w = (SEQ - c0) >> 2;
        const float4 z4 = make_float4(0.f, 0.f, 0.f, 0.f);
        for (int r = warp; r < 128; r += 8) {
            float4* rowp = (float4*)(P + ((size_t)bh * SEQ + q0 + r) * SEQ + c0);
            for (int cc = lane; cc < w; cc += 32)
                __stcs(rowp + cc, z4);
        }
    }

    const int rl = warp * 16 + (lane >> 2), rh = rl + 8;
    const int qrl = q0 + rl, qrh = q0 + rh;
    const bool mql = mask[(size_t)b * SEQ + qrl] != 0.f;
    const bool mqh = mask[(size_t)b * SEQ + qrh] != 0.f;
    const int dcol = 2 * (lane & 3);
    const int tcl = qrl - mn - dcol;
    const int tch = qrh - mn - dcol;

    const uint32_t cbq = (uint32_t)(lane & 8) << 1;
    const uint32_t cbv = (uint32_t)(g >> 1) << 4;
    const uint32_t ka0 = swzrow(((g >> 1) << 3) + r8);
    const uint32_t va0 = swzrow(((g & 1) << 3) + r8);
    const uint32_t qrowswz = swzrow(warp * 16 + ((g & 1) << 3) + r8);

    __syncthreads();

    uint32_t qf[4][4];
    #pragma unroll
    for (int s = 0; s < 4; s++)
        ldsm4(qf[s], smb + (qrowswz ^ (cbv | (s << 5))));

    float o[8][4];
    #pragma unroll
    for (int j = 0; j < 8; j++)
        o[j][0] = o[j][1] = o[j][2] = o[j][3] = 0.f;
    float rsl = 0.f, rsh = 0.f;

    // ======================= PHASE 1: rowsums + PV (no P stores) ============
    for (int t = 0; t <= qt; t++) {
        const int cur = t & 1, nxt = cur ^ 1;
        const bool hasNext = (t < qt);
        const uint32_t Kc = smb + KBUF(cur);
        const uint32_t Vc = smb + VBUF(cur);
        const int k0 = t * 128;
        const bool diag = (t == qt);
        const float* Kg = K + ((size_t)bh * SEQ + k0 + 128) * HD + base_elem;
        const float* Vg = V + ((size_t)bh * SEQ + k0 + 128) * HD + base_elem;

        #pragma unroll
        for (int h = 0; h < 4; h++) {
            float4 pk[2], pv[2];
            if (hasNext) {
                #pragma unroll
                for (int u = 0; u < 2; u++) {
                    pk[u] = *(const float4*)(Kg + (2 * h + u) * 1024);
                    pv[u] = *(const float4*)(Vg + (2 * h + u) * 1024);
                }
            }

            if (!(diag && (2 * h > warp))) {
                float c[4][4];
                #pragma unroll
                for (int j = 0; j < 4; j++)
                    c[j][0] = c[j][1] = c[j][2] = c[j][3] = 0.f;

                #pragma unroll
                for (int s = 0; s < 4; s++) {
                    #pragma unroll
                    for (int pp = 0; pp < 2; pp++) {
                        uint32_t kh[4];
                        ldsm4(kh, Kc + ((ka0 + ((uint32_t)(2 * h + pp) << 11)) ^ (cbq | (s << 5))));
                        mma_f16(c[2 * pp],     qf[s], kh[0], kh[1]);
                        mma_f16(c[2 * pp + 1], qf[s], kh[2], kh[3]);
                    }
                }

                if (!diag) {
                    #pragma unroll
                    for (int jl = 0; jl < 4; jl++) {
                        c[jl][0] = mql ? exp2f(c[jl][0]) : 0.f;
                        c[jl][1] = mql ? exp2f(c[jl][1]) : 0.f;
                        c[jl][2] = mqh ? exp2f(c[jl][2]) : 0.f;
                        c[jl][3] = mqh ? exp2f(c[jl][3]) : 0.f;
                        rsl += c[jl][0] + c[jl][1];
                        rsh += c[jl][2] + c[jl][3];
                    }
                } else {
                    #pragma unroll
                    for (int jl = 0; jl < 4; jl++) {
                        int bs = k0 + h * 32 + jl * 8;
                        c[jl][0] = (mql && bs <= tcl    ) ? exp2f(c[jl][0]) : 0.f;
                        c[jl][1] = (mql && bs <= tcl - 1) ? exp2f(c[jl][1]) : 0.f;
                        c[jl][2] = (mqh && bs <= tch    ) ? exp2f(c[jl][2]) : 0.f;
                        c[jl][3] = (mqh && bs <= tch - 1) ? exp2f(c[jl][3]) : 0.f;
                        rsl += c[jl][0] + c[jl][1];
                        rsh += c[jl][2] + c[jl][3];
                    }
                }

                #pragma unroll
                for (int sl = 0; sl < 2; sl++) {
                    uint32_t af[4];
                    af[0] = pack2h(c[2 * sl][0],     c[2 * sl][1]);
                    af[1] = pack2h(c[2 * sl][2],     c[2 * sl][3]);
                    af[2] = pack2h(c[2 * sl + 1][0], c[2 * sl + 1][1]);
                    af[3] = pack2h(c[2 * sl + 1][2], c[2 * sl + 1][3]);
                    uint32_t vrow = va0 + ((uint32_t)(2 * h + sl) << 11);
                    #pragma unroll
                    for (int p = 0; p < 4; p++) {
                        uint32_t bhr[4];
                        ldsm4t(bhr, Vc + (vrow ^ (cbv | (p << 5))));
                        mma_f16(o[2 * p],     af, bhr[0], bhr[1]);
                        mma_f16(o[2 * p + 1], af, bhr[2], bhr[3]);
                    }
                }
            }

            if (hasNext) {
                #pragma unroll
                for (int u = 0; u < 2; u++) {
                    uint32_t off = cvt0 + (2 * h + u) * 2048;
                    *(uint2*)(sm + KBUF(nxt) + off) = make_uint2(
                        pack2h(pk[u].x, pk[u].y), pack2h(pk[u].z, pk[u].w));
                    *(uint2*)(sm + VBUF(nxt) + off) = make_uint2(
                        pack2h(pv[u].x, pv[u].y), pack2h(pv[u].z, pv[u].w));
                }
            }
        }
        __syncthreads();
    }

    // ---- rowsums -> inv; O store (scaled, streaming) ----
    rsl += __shfl_xor_sync(0xffffffffu, rsl, 1);
    rsl += __shfl_xor_sync(0xffffffffu, rsl, 2);
    rsh += __shfl_xor_sync(0xffffffffu, rsh, 1);
    rsh += __shfl_xor_sync(0xffffffffu, rsh, 2);
    const float il = (rsl > 0.f) ? (1.f / rsl) : 0.f;
    const float ih = (rsh > 0.f) ? (1.f / rsh) : 0.f;

    #pragma unroll
    for (int j = 0; j < 8; j++) {
        __stcs((float2*)(O + ((size_t)bh * SEQ + qrl) * HD + j * 8 + dcol),
               make_float2(o[j][0] * il, o[j][1] * il));
        __stcs((float2*)(O + ((size_t)bh * SEQ + qrh) * HD + j * 8 + dcol),
               make_float2(o[j][2] * ih, o[j][3] * ih));
    }

    // ======================= PHASE 2: recompute + store normalized P ========
    // Backwards: K tile qt still resident in buffer (qt&1) from phase 1.
    // Store path: warp-private smem bounce slab (V area, free now), then
    // fully-coalesced drain: 8 lanes per 128B row, 2 rows-groups x 2 halves.
    // Slab: 16 rows x 192B stride; write swizzle col ^= 16B*(row&3)
    // (conflict-free STS.64 phases and LDS.128 phases, checked per-bank).
    const int r_l = lane >> 2;                         // fragment row 0..7
    const int WSo = (int)VBUF(0) + warp * 4096;        // slab byte offset
    const uint32_t xsw = (uint32_t)(r_l & 3) << 4;
    char* const slab_l = sm + WSo + r_l * 192;
    char* const slab_h = slab_l + 8 * 192;
    // drain: row dr = 4i + (lane>>3), granule lane&7, unswizzle ^(dr&3)
    const int drow = lane >> 3;                        // 0..3
    const uint32_t dgr = (uint32_t)((lane & 7) ^ drow) << 4;
    char* const drn = sm + WSo + drow * 192 + dgr;     // +i*768, +half*1536
    float* const Pst = P + ((size_t)bh * SEQ + q0 + warp * 16 + drow) * SEQ
                         + (lane & 7) * 4;             // +i*4*SEQ, +half*8*SEQ

    float2* const Prl = (float2*)(P + ((size_t)bh * SEQ + qrl) * SEQ) + (lane & 3);
    float2* const Prh = (float2*)(P + ((size_t)bh * SEQ + qrh) * SEQ) + (lane & 3);

    for (int t = qt; t >= 0; t--) {
        const int cur = t & 1, nxt = cur ^ 1;
        const bool hasNext = (t > 0);
        const uint32_t Kc = smb + KBUF(cur);
        const int k0 = t * 128;
        const bool diag = (t == qt);
        const float* Kg = K + ((size_t)bh * SEQ + k0 - 128) * HD + base_elem;  // tile t-1

        #pragma unroll
        for (int h = 0; h < 4; h++) {
            float4 pk[2];
            if (hasNext) {
                #pragma unroll
                for (int u = 0; u < 2; u++)
                    pk[u] = *(const float4*)(Kg + (2 * h + u) * 1024);
            }

            if (diag && (2 * h > warp)) {
                #pragma unroll
                for (int jl = 0; jl < 4; jl++) {
                    __stcs(Prl + (k0 >> 1) + h * 16 + jl * 4, make_float2(0.f, 0.f));
                    __stcs(Prh + (k0 >> 1) + h * 16 + jl * 4, make_float2(0.f, 0.f));
                }
            } else {
                float c[4][4];
                #pragma unroll
                for (int j = 0; j < 4; j++)
                    c[j][0] = c[j][1] = c[j][2] = c[j][3] = 0.f;

                #pragma unroll
                for (int s = 0; s < 4; s++) {
                    #pragma unroll
                    for (int pp = 0; pp < 2; pp++) {
                        uint32_t kh[4];
                        ldsm4(kh, Kc + ((ka0 + ((uint32_t)(2 * h + pp) << 11)) ^ (cbq | (s << 5))));
                        mma_f16(c[2 * pp],     qf[s], kh[0], kh[1]);
                        mma_f16(c[2 * pp + 1], qf[s], kh[2], kh[3]);
                    }
                }

                __syncwarp();   // prior chunk's drain done before overwrite
                if (!diag) {
                    #pragma unroll
                    for (int jl = 0; jl < 4; jl++) {
                        uint32_t co = (uint32_t)(jl * 32 + dcol * 4) ^ xsw;
                        *(float2*)(slab_l + co) = make_float2(
                            mql ? exp2f(c[jl][0]) * il : 0.f,
                            mql ? exp2f(c[jl][1]) * il : 0.f);
                        *(float2*)(slab_h + co) = make_float2(
                            mqh ? exp2f(c[jl][2]) * ih : 0.f,
                            mqh ? exp2f(c[jl][3]) * ih : 0.f);
                    }
                } else {
                    #pragma unroll
                    for (int jl = 0; jl < 4; jl++) {
                        int bs = k0 + h * 32 + jl * 8;
                        uint32_t co = (uint32_t)(jl * 32 + dcol * 4) ^ xsw;
                        *(float2*)(slab_l + co) = make_float2(
                            (mql && bs <= tcl    ) ? exp2f(c[jl][0]) * il : 0.f,
                            (mql && bs <= tcl - 1) ? exp2f(c[jl][1]) * il : 0.f);
                        *(float2*)(slab_h + co) = make_float2(
                            (mqh && bs <= tch    ) ? exp2f(c[jl][2]) * ih : 0.f,
                            (mqh && bs <= tch - 1) ? exp2f(c[jl][3]) * ih : 0.f);
                    }
                }
                __syncwarp();
                // drain: 2 row-groups x 2 halves, fully coalesced 128B lines
                #pragma unroll
                for (int i = 0; i < 2; i++) {
                    float4 f0 = *(float4*)(drn + i * 768);
                    float4 f1 = *(float4*)(drn + i * 768 + 1536);
                    __stcs((float4*)(Pst + (size_t)i * 4 * SEQ + k0 + h * 32), f0);
                    __stcs((float4*)(Pst + (size_t)i * 4 * SEQ + 8 * SEQ + k0 + h * 32), f1);
                }
            }

            if (hasNext) {
                #pragma unroll
                for (int u = 0; u < 2; u++) {
                    uint32_t off = cvt0 + (2 * h + u) * 2048;
                    *(uint2*)(sm + KBUF(nxt) + off) = make_uint2(
                        pack2h(pk[u].x, pk[u].y), pack2h(pk[u].z, pk[u].w));
                }
            }
        }
        __syncthreads();
    }
}

// ---------------------------------------------------------------------------
extern "C" void kernel_launch(void* const* d_in, const int* in_sizes, int n_in,
                              void* d_out, int out_size)
{
    const float* Q        = (const float*)d_in[0];
    const float* K        = (const float*)d_in[1];
    const float* V        = (const float*)d_in[2];
    const float* mask     = (const float*)d_in[3];
    const int*   mask_now = (const int*)d_in[4];

    float* O = (float*)d_out;                      // [B,H,S,D]
    float* P = O + (size_t)NBH * SEQ * HD;         // [B,H,S,S]

    cudaFuncSetAttribute(k_attn, cudaFuncAttributeMaxDynamicSharedMemorySize, 82432);

    k_attn<<<dim3(16, NBH), 256, 82432>>>(Q, K, V, mask, mask_now, P, O);
}

// round 15
// speedup vs baseline: 2.3350x; 1.0788x over previous
#include <cuda_runtime.h>
#include <cuda_fp16.h>
#include <cstdint>

#define SEQ 2048
#define HD  64
#define NBH 32

#define SWZ(x) ((x) ^ (((x) >> 3) & 0x70))
#define NEG_INF __int_as_float(0xff800000)

__device__ __forceinline__ uint32_t smem_u32(const void* p) {
    uint32_t a;
    asm("{ .reg .u64 t; cvta.to.shared.u64 t, %1; cvt.u32.u64 %0, t; }"
        : "=r"(a) : "l"(p));
    return a;
}
__device__ __forceinline__ void ldsm4(uint32_t* d, uint32_t a) {
    asm volatile("ldmatrix.sync.aligned.m8n8.x4.shared.b16 {%0,%1,%2,%3}, [%4];"
        : "=r"(d[0]), "=r"(d[1]), "=r"(d[2]), "=r"(d[3]) : "r"(a));
}
__device__ __forceinline__ void ldsm4t(uint32_t* d, uint32_t a) {
    asm volatile("ldmatrix.sync.aligned.m8n8.x4.trans.shared.b16 {%0,%1,%2,%3}, [%4];"
        : "=r"(d[0]), "=r"(d[1]), "=r"(d[2]), "=r"(d[3]) : "r"(a));
}
__device__ __forceinline__ void mma_f16(float* c, const uint32_t* a,
                                        uint32_t b0, uint32_t b1) {
    asm volatile(
        "mma.sync.aligned.m16n8k16.row.col.f32.f16.f16.f32 "
        "{%0,%1,%2,%3}, {%4,%5,%6,%7}, {%8,%9}, {%0,%1,%2,%3};"
        : "+f"(c[0]), "+f"(c[1]), "+f"(c[2]), "+f"(c[3])
        : "r"(a[0]), "r"(a[1]), "r"(a[2]), "r"(a[3]), "r"(b0), "r"(b1));
}
__device__ __forceinline__ uint32_t pack2h(float x0, float x1) {
    __half2 h = __floats2half2_rn(x0, x1);
    return *reinterpret_cast<uint32_t*>(&h);
}
__device__ __forceinline__ uint32_t swzrow(int r) {
    uint32_t x = (uint32_t)r << 7;
    return x ^ ((x >> 3) & 0x70);
}
// bare MUFU.EX2 (approx handles -inf -> +0 per PTX spec)
__device__ __forceinline__ float ex2(float x) {
    float r;
    asm("ex2.approx.ftz.f32 %0, %1;" : "=f"(r) : "f"(x));
    return r;
}

// smem map: QF 0..16K (persistent), K dbuf 16K..48K, V dbuf 48K..80K
// phase 2 reuses the V area (free) as warp-private store-bounce slabs.
#define KBUF(b) (16384u + (b) * 16384u)
#define VBUF(b) (49152u + (b) * 16384u)

// Q pre-scale: (1/8) * log2(e) -> scores in log2 domain -> ex2
#define QSCALE 0.1803368801111204f

__global__ __launch_bounds__(256, 2) void k_attn(
    const float* __restrict__ Q, const float* __restrict__ K,
    const float* __restrict__ V, const float* __restrict__ mask,
    const int* __restrict__ mask_now,
    float* __restrict__ P, float* __restrict__ O)
{
    extern __shared__ char sm[];
    const uint32_t smb = smem_u32(sm);
    const int tid = threadIdx.x, lane = tid & 31, warp = tid >> 5;
    const int g = lane >> 3, r8 = lane & 7;
    const int qt = 15 - blockIdx.x, bh = blockIdx.y, b = bh >> 4;
    const int q0 = qt * 128;
    const int mn = mask_now[0];

    // per-thread staging bases (slice s in [0,8): gmem +s*1024 elems, smem +s*2048)
    const int base_elem = (tid >> 4) * HD + (tid & 15) * 4;
    const uint32_t cvt0 = SWZ((uint32_t)((tid >> 4) * 128 + (tid & 15) * 8));

    // ---- stage Q (pre-scaled) + tile-0 K/V fp16 planes ----
    {
        const float* Qg = Q + ((size_t)bh * SEQ + q0) * HD + base_elem;
        const float* Kg = K + (size_t)bh * SEQ * HD + base_elem;
        const float* Vg = V + (size_t)bh * SEQ * HD + base_elem;
        #pragma unroll
        for (int s = 0; s < 8; s++) {
            uint32_t off = cvt0 + s * 2048;
            float4 v = *(const float4*)(Qg + s * 1024);
            *(uint2*)(sm + 0 + off) = make_uint2(
                pack2h(v.x * QSCALE, v.y * QSCALE),
                pack2h(v.z * QSCALE, v.w * QSCALE));
            v = *(const float4*)(Kg + s * 1024);
            *(uint2*)(sm + KBUF(0) + off) = make_uint2(
                pack2h(v.x, v.y), pack2h(v.z, v.w));
            v = *(const float4*)(Vg + s * 1024);
            *(uint2*)(sm + VBUF(0) + off) = make_uint2(
                pack2h(v.x, v.y), pack2h(v.z, v.w));
        }
    }

    // zero-fill P cols [q0+128, SEQ) -- streaming stores
    {
        const int c0 = q0 + 128;
        const int w = (SEQ - c0) >> 2;
        const float4 z4 = make_float4(0.f, 0.f, 0.f, 0.f);
        for (int r = warp; r < 128; r += 8) {
            float4* rowp = (float4*)(P + ((size_t)bh * SEQ + q0 + r) * SEQ + c0);
            for (int cc = lane; cc < w; cc += 32)
                __stcs(rowp + cc, z4);
        }
    }

    const int rl = warp * 16 + (lane >> 2), rh = rl + 8;
    const int qrl = q0 + rl, qrh = q0 + rh;
    // mask folded into the MMA accumulator bias: -inf -> ex2 -> exact 0
    const float biasl = (mask[(size_t)b * SEQ + qrl] != 0.f) ? 0.f : NEG_INF;
    const float biash = (mask[(size_t)b * SEQ + qrh] != 0.f) ? 0.f : NEG_INF;
    const int dcol = 2 * (lane & 3);
    const int tcl = qrl - mn - dcol;
    const int tch = qrh - mn - dcol;

    const uint32_t cbq = (uint32_t)(lane & 8) << 1;
    const uint32_t cbv = (uint32_t)(g >> 1) << 4;
    const uint32_t ka0 = swzrow(((g >> 1) << 3) + r8);
    const uint32_t va0 = swzrow(((g & 1) << 3) + r8);
    const uint32_t qrowswz = swzrow(warp * 16 + ((g & 1) << 3) + r8);

    __syncthreads();

    uint32_t qf[4][4];
    #pragma unroll
    for (int s = 0; s < 4; s++)
        ldsm4(qf[s], smb + (qrowswz ^ (cbv | (s << 5))));

    float o[8][4];
    #pragma unroll
    for (int j = 0; j < 8; j++)
        o[j][0] = o[j][1] = o[j][2] = o[j][3] = 0.f;
    float rsl = 0.f, rsh = 0.f;

    // ======================= PHASE 1: rowsums + PV (no P stores) ============
    for (int t = 0; t <= qt; t++) {
        const int cur = t & 1, nxt = cur ^ 1;
        const bool hasNext = (t < qt);
        const uint32_t Kc = smb + KBUF(cur);
        const uint32_t Vc = smb + VBUF(cur);
        const int k0 = t * 128;
        const bool diag = (t == qt);
        const float* Kg = K + ((size_t)bh * SEQ + k0 + 128) * HD + base_elem;
        const float* Vg = V + ((size_t)bh * SEQ + k0 + 128) * HD + base_elem;

        #pragma unroll
        for (int h = 0; h < 4; h++) {
            float4 pk[2], pv[2];
            if (hasNext) {
                #pragma unroll
                for (int u = 0; u < 2; u++) {
                    pk[u] = *(const float4*)(Kg + (2 * h + u) * 1024);
                    pv[u] = *(const float4*)(Vg + (2 * h + u) * 1024);
                }
            }

            if (!(diag && (2 * h > warp))) {
                float c[4][4];
                #pragma unroll
                for (int j = 0; j < 4; j++) {
                    c[j][0] = c[j][1] = biasl;
                    c[j][2] = c[j][3] = biash;
                }

                #pragma unroll
                for (int s = 0; s < 4; s++) {
                    #pragma unroll
                    for (int pp = 0; pp < 2; pp++) {
                        uint32_t kh[4];
                        ldsm4(kh, Kc + ((ka0 + ((uint32_t)(2 * h + pp) << 11)) ^ (cbq | (s << 5))));
                        mma_f16(c[2 * pp],     qf[s], kh[0], kh[1]);
                        mma_f16(c[2 * pp + 1], qf[s], kh[2], kh[3]);
                    }
                }

                if (!diag) {
                    #pragma unroll
                    for (int jl = 0; jl < 4; jl++) {
                        c[jl][0] = ex2(c[jl][0]);
                        c[jl][1] = ex2(c[jl][1]);
                        c[jl][2] = ex2(c[jl][2]);
                        c[jl][3] = ex2(c[jl][3]);
                        rsl += c[jl][0] + c[jl][1];
                        rsh += c[jl][2] + c[jl][3];
                    }
                } else {
                    #pragma unroll
                    for (int jl = 0; jl < 4; jl++) {
                        int bs = k0 + h * 32 + jl * 8;
                        c[jl][0] = (bs <= tcl    ) ? ex2(c[jl][0]) : 0.f;
                        c[jl][1] = (bs <= tcl - 1) ? ex2(c[jl][1]) : 0.f;
                        c[jl][2] = (bs <= tch    ) ? ex2(c[jl][2]) : 0.f;
                        c[jl][3] = (bs <= tch - 1) ? ex2(c[jl][3]) : 0.f;
                        rsl += c[jl][0] + c[jl][1];
                        rsh += c[jl][2] + c[jl][3];
                    }
                }

                #pragma unroll
                for (int sl = 0; sl < 2; sl++) {
                    uint32_t af[4];
                    af[0] = pack2h(c[2 * sl][0],     c[2 * sl][1]);
                    af[1] = pack2h(c[2 * sl][2],     c[2 * sl][3]);
                    af[2] = pack2h(c[2 * sl + 1][0], c[2 * sl + 1][1]);
                    af[3] = pack2h(c[2 * sl + 1][2], c[2 * sl + 1][3]);
                    uint32_t vrow = va0 + ((uint32_t)(2 * h + sl) << 11);
                    #pragma unroll
                    for (int p = 0; p < 4; p++) {
                        uint32_t bhr[4];
                        ldsm4t(bhr, Vc + (vrow ^ (cbv | (p << 5))));
                        mma_f16(o[2 * p],     af, bhr[0], bhr[1]);
                        mma_f16(o[2 * p + 1], af, bhr[2], bhr[3]);
                    }
                }
            }

            if (hasNext) {
                #pragma unroll
                for (int u = 0; u < 2; u++) {
                    uint32_t off = cvt0 + (2 * h + u) * 2048;
                    *(uint2*)(sm + KBUF(nxt) + off) = make_uint2(
                        pack2h(pk[u].x, pk[u].y), pack2h(pk[u].z, pk[u].w));
                    *(uint2*)(sm + VBUF(nxt) + off) = make_uint2(
                        pack2h(pv[u].x, pv[u].y), pack2h(pv[u].z, pv[u].w));
                }
            }
        }
        __syncthreads();
    }

    // ---- rowsums -> inv + log-bias; O store (scaled, streaming) ----
    rsl += __shfl_xor_sync(0xffffffffu, rsl, 1);
    rsl += __shfl_xor_sync(0xffffffffu, rsl, 2);
    rsh += __shfl_xor_sync(0xffffffffu, rsh, 1);
    rsh += __shfl_xor_sync(0xffffffffu, rsh, 2);
    const float il = (rsl > 0.f) ? (1.f / rsl) : 0.f;
    const float ih = (rsh > 0.f) ? (1.f / rsh) : 0.f;
    const float lbl = (rsl > 0.f) ? -__log2f(rsl) : NEG_INF;   // log2(1/l)
    const float lbh = (rsh > 0.f) ? -__log2f(rsh) : NEG_INF;

    #pragma unroll
    for (int j = 0; j < 8; j++) {
        __stcs((float2*)(O + ((size_t)bh * SEQ + qrl) * HD + j * 8 + dcol),
               make_float2(o[j][0] * il, o[j][1] * il));
        __stcs((float2*)(O + ((size_t)bh * SEQ + qrh) * HD + j * 8 + dcol),
               make_float2(o[j][2] * ih, o[j][3] * ih));
    }

    // ======================= PHASE 2: recompute + store normalized P ========
    // Backwards: K tile qt still resident in buffer (qt&1) from phase 1.
    // Accumulator pre-biased with log2(1/l): P = ex2(c) directly (mask
    // subsumed: l==0 -> bias=-inf -> 0). Bounce-slab drain as in R14.
    const int r_l = lane >> 2;
    const int WSo = (int)VBUF(0) + warp * 4096;
    const uint32_t xsw = (uint32_t)(r_l & 3) << 4;
    char* const slab_l = sm + WSo + r_l * 192;
    char* const slab_h = slab_l + 8 * 192;
    const int drow = lane >> 3;
    const uint32_t dgr = (uint32_t)((lane & 7) ^ drow) << 4;
    char* const drn = sm + WSo + drow * 192 + dgr;
    float* const Pst = P + ((size_t)bh * SEQ + q0 + warp * 16 + drow) * SEQ
                         + (lane & 7) * 4;

    float2* const Prl = (float2*)(P + ((size_t)bh * SEQ + qrl) * SEQ) + (lane & 3);
    float2* const Prh = (float2*)(P + ((size_t)bh * SEQ + qrh) * SEQ) + (lane & 3);

    for (int t = qt; t >= 0; t--) {
        const int cur = t & 1, nxt = cur ^ 1;
        const bool hasNext = (t > 0);
        const uint32_t Kc = smb + KBUF(cur);
        const int k0 = t * 128;
        const bool diag = (t == qt);
        const float* Kg = K + ((size_t)bh * SEQ + k0 - 128) * HD + base_elem;

        #pragma unroll
        for (int h = 0; h < 4; h++) {
            float4 pk[2];
            if (hasNext) {
                #pragma unroll
                for (int u = 0; u < 2; u++)
                    pk[u] = *(const float4*)(Kg + (2 * h + u) * 1024);
            }

            if (diag && (2 * h > warp)) {
                #pragma unroll
                for (int jl = 0; jl < 4; jl++) {
                    __stcs(Prl + (k0 >> 1) + h * 16 + jl * 4, make_float2(0.f, 0.f));
                    __stcs(Prh + (k0 >> 1) + h * 16 + jl * 4, make_float2(0.f, 0.f));
                }
            } else {
                float c[4][4];
                #pragma unroll
                for (int j = 0; j < 4; j++) {
                    c[j][0] = c[j][1] = lbl;
                    c[j][2] = c[j][3] = lbh;
                }

                #pragma unroll
                for (int s = 0; s < 4; s++) {
                    #pragma unroll
                    for (int pp = 0; pp < 2; pp++) {
                        uint32_t kh[4];
                        ldsm4(kh, Kc + ((ka0 + ((uint32_t)(2 * h + pp) << 11)) ^ (cbq | (s << 5))));
                        mma_f16(c[2 * pp],     qf[s], kh[0], kh[1]);
                        mma_f16(c[2 * pp + 1], qf[s], kh[2], kh[3]);
                    }
                }

                __syncwarp();   // prior chunk's drain done before overwrite
                if (!diag) {
                    #pragma unroll
                    for (int jl = 0; jl < 4; jl++) {
                        uint32_t co = (uint32_t)(jl * 32 + dcol * 4) ^ xsw;
                        *(float2*)(slab_l + co) =
                            make_float2(ex2(c[jl][0]), ex2(c[jl][1]));
                        *(float2*)(slab_h + co) =
                            make_float2(ex2(c[jl][2]), ex2(c[jl][3]));
                    }
                } else {
                    #pragma unroll
                    for (int jl = 0; jl < 4; jl++) {
                        int bs = k0 + h * 32 + jl * 8;
                        uint32_t co = (uint32_t)(jl * 32 + dcol * 4) ^ xsw;
                        *(float2*)(slab_l + co) = make_float2(
                            (bs <= tcl    ) ? ex2(c[jl][0]) : 0.f,
                            (bs <= tcl - 1) ? ex2(c[jl][1]) : 0.f);
                        *(float2*)(slab_h + co) = make_float2(
                            (bs <= tch    ) ? ex2(c[jl][2]) : 0.f,
                            (bs <= tch - 1) ? ex2(c[jl][3]) : 0.f);
                    }
                }
                __syncwarp();
                #pragma unroll
                for (int i = 0; i < 2; i++) {
                    float4 f0 = *(float4*)(drn + i * 768);
                    float4 f1 = *(float4*)(drn + i * 768 + 1536);
                    __stcs((float4*)(Pst + (size_t)i * 4 * SEQ + k0 + h * 32), f0);
                    __stcs((float4*)(Pst + (size_t)i * 4 * SEQ + 8 * SEQ + k0 + h * 32), f1);
                }
            }

            if (hasNext) {
                #pragma unroll
                for (int u = 0; u < 2; u++) {
                    uint32_t off = cvt0 + (2 * h + u) * 2048;
                    *(uint2*)(sm + KBUF(nxt) + off) = make_uint2(
                        pack2h(pk[u].x, pk[u].y), pack2h(pk[u].z, pk[u].w));
                }
            }
        }
        __syncthreads();
    }
}

// ---------------------------------------------------------------------------
extern "C" void kernel_launch(void* const* d_in, const int* in_sizes, int n_in,
                              void* d_out, int out_size)
{
    const float* Q        = (const float*)d_in[0];
    const float* K        = (const float*)d_in[1];
    const float* V        = (const float*)d_in[2];
    const float* mask     = (const float*)d_in[3];
    const int*   mask_now = (const int*)d_in[4];

    float* O = (float*)d_out;                      // [B,H,S,D]
    float* P = O + (size_t)NBH * SEQ * HD;         // [B,H,S,S]

    cudaFuncSetAttribute(k_attn, cudaFuncAttributeMaxDynamicSharedMemorySize, 82432);

    k_attn<<<dim3(16, NBH), 256, 82432>>>(Q, K, V, mask, mask_now, P, O);
}